// round 9
// baseline (speedup 1.0000x reference)
#include <cuda_runtime.h>
#include <cuda_bf16.h>
#include <cuda_fp16.h>
#include <cstdint>

namespace {
constexpr int SEQ = 2048;
constexpr int BT  = 2;
constexpr int DM  = 1024;
constexpr int NH  = 16;
constexpr int NTOK = BT * SEQ;     // 4096
constexpr float SCLOG2E = 0.125f * 1.4426950408889634f;  // scale * log2(e)
}

// ---------------- device scratch (allocation-free) ----------------
__device__ __half g_q [NTOK * DM];                   // Q, fp16 single
__device__ __half g_k [NTOK * DM];                   // K, fp16 single
__device__ float  g_V [NTOK * DM];
__device__ __half g_vt[NTOK * DM];                   // [b][h][d][s], fp16 single
__device__ __half g_c [NTOK * DM];                   // context, fp16 single
__device__ float  g_Z [BT * SEQ * SEQ];              // reciprocal denom
__device__ __half g_E [(size_t)BT * NH * SEQ * SEQ]; // exp(scores), [b][h][q][k]
__device__ __half g_x [NTOK * DM];                   // x, fp16 single
__device__ __half g_wh[4][DM * DM], g_wl[4][DM * DM];

// ---------------- tiny PTX helpers (sm_103-safe) ----------------
__device__ __forceinline__ uint32_t smem_u32(const void* p) {
    uint32_t a;
    asm("{ .reg .u64 t; cvta.to.shared.u64 t, %1; cvt.u32.u64 %0, t; }" : "=r"(a) : "l"(p));
    return a;
}
__device__ __forceinline__ void cp16(uint32_t dst, const void* src) {
    asm volatile("cp.async.cg.shared.global [%0], [%1], 16;" :: "r"(dst), "l"(src) : "memory");
}
__device__ __forceinline__ void cp_commit() {
    asm volatile("cp.async.commit_group;" ::: "memory");
}
template <int N> __device__ __forceinline__ void cp_wait() {
    asm volatile("cp.async.wait_group %0;" :: "n"(N) : "memory");
}
__device__ __forceinline__ void mma16816(float* d, const uint32_t* a, const uint32_t* b) {
    asm volatile(
        "mma.sync.aligned.m16n8k16.row.col.f32.f16.f16.f32 "
        "{%0,%1,%2,%3}, {%4,%5,%6,%7}, {%8,%9}, {%0,%1,%2,%3};"
        : "+f"(d[0]), "+f"(d[1]), "+f"(d[2]), "+f"(d[3])
        : "r"(a[0]), "r"(a[1]), "r"(a[2]), "r"(a[3]), "r"(b[0]), "r"(b[1]));
}
__device__ __forceinline__ float ex2(float x) {
    float y; asm("ex2.approx.ftz.f32 %0, %1;" : "=f"(y) : "f"(x)); return y;
}
__device__ __forceinline__ float frcp(float x) {
    float y; asm("rcp.approx.ftz.f32 %0, %1;" : "=f"(y) : "f"(x)); return y;
}
// pack two fp32 -> f16x2 reg: low half = `lo` (lower column index)
__device__ __forceinline__ uint32_t packh2(float lo, float hi) {
    uint32_t r; asm("cvt.rn.f16x2.f32 %0, %1, %2;" : "=r"(r) : "f"(hi), "f"(lo)); return r;
}
__device__ __forceinline__ uint32_t hmul2u(uint32_t a, uint32_t b) {
    __half2 r = __hmul2(*(const __half2*)&a, *(const __half2*)&b);
    return *(uint32_t*)&r;
}
// split (x,y) into hi f16x2 and residual-lo f16x2
__device__ __forceinline__ void split2h(float x, float y, uint32_t& hi, uint32_t& lo) {
    __half hx = __float2half_rn(x), hy = __float2half_rn(y);
    float rx = x - __half2float(hx), ry = y - __half2float(hy);
    __half2 h2; h2.x = hx; h2.y = hy;
    hi = *(uint32_t*)&h2;
    lo = packh2(rx, ry);
}

// ---------------------------------------------------------------------------
// fp32 -> fp16 single (for x)
// ---------------------------------------------------------------------------
__global__ __launch_bounds__(256)
void cvt_h(const float* __restrict__ in, __half* __restrict__ out, int n)
{
    int i = (blockIdx.x * 256 + threadIdx.x) * 4;
    if (i >= n) return;
    float4 v = *(const float4*)(in + i);
    ushort4 o;
    o.x = __half_as_ushort(__float2half_rn(v.x));
    o.y = __half_as_ushort(__float2half_rn(v.y));
    o.z = __half_as_ushort(__float2half_rn(v.z));
    o.w = __half_as_ushort(__float2half_rn(v.w));
    *(ushort4*)((unsigned short*)out + i) = o;
}

// all 4 weights: fp32 -> split fp16 hi/lo
__global__ __launch_bounds__(256)
void cvt_w4(const float* __restrict__ W0, const float* __restrict__ W1,
            const float* __restrict__ W2, const float* __restrict__ W3,
            __half* __restrict__ hi, __half* __restrict__ lo)
{
    const int NW = DM * DM;
    const float* in = (blockIdx.y == 0) ? W0 : (blockIdx.y == 1) ? W1
                    : (blockIdx.y == 2) ? W2 : W3;
    int i = (blockIdx.x * 256 + threadIdx.x) * 4;
    size_t o = (size_t)blockIdx.y * NW + i;
    float4 v = *(const float4*)(in + i);
    float a[4] = {v.x, v.y, v.z, v.w};
    unsigned short hs[4], ls[4];
#pragma unroll
    for (int j = 0; j < 4; j++) {
        __half h = __float2half_rn(a[j]);
        float r = a[j] - __half2float(h);
        hs[j] = __half_as_ushort(h);
        ls[j] = __half_as_ushort(__float2half_rn(r));
    }
    *(ushort4*)((unsigned short*)hi + o) = make_ushort4(hs[0], hs[1], hs[2], hs[3]);
    *(ushort4*)((unsigned short*)lo + o) = make_ushort4(ls[0], ls[1], ls[2], ls[3]);
}

// ---------------------------------------------------------------------------
// HMMA 2-term split-fp16 GEMM: C = A * B^T + bias (A fp16; B = Bh + Bl)
// OUT: 0 = fp32 Cf, 1 = fp16 single Ch
// ---------------------------------------------------------------------------
namespace {
constexpr int G_RSB   = 144;
constexpr int G_TILE  = 128 * G_RSB;       // 18432
constexpr int G_STAGE = 3 * G_TILE;        // 55296 (A, Bh, Bl)
constexpr int G_SMEM  = 2 * G_STAGE;       // 110592
}

template <int OUT>
__global__ __launch_bounds__(256, 2)
void gemm_mma(const __half* __restrict__ A,
              const __half* __restrict__ Bh, const __half* __restrict__ Bl,
              const float* __restrict__ bias,
              float* __restrict__ Cf, __half* __restrict__ Ch,
              int M, int N, int K)
{
    extern __shared__ __align__(16) char smem[];
    const uint32_t sb = smem_u32(smem);
    const int tid = threadIdx.x, lane = tid & 31, wid = tid >> 5;
    const int wm = wid >> 2, wn = wid & 3;
    const int r = lane >> 2, c = lane & 3;
    const int m0 = blockIdx.y * 128, n0 = blockIdx.x * 128;
    const int KT = K / 64;

    float acc[4][4][4];
#pragma unroll
    for (int i = 0; i < 4; i++)
#pragma unroll
        for (int j = 0; j < 4; j++)
#pragma unroll
            for (int q = 0; q < 4; q++) acc[i][j][q] = 0.f;

    auto issue = [&](int kt, int s) {
        const int k0 = kt * 64;
#pragma unroll
        for (int a = 0; a < 3; a++) {
            const __half* g = (a == 0) ? A : (a == 1) ? Bh : Bl;
            const int rbase = (a == 0) ? m0 : n0;
            const uint32_t dstb = sb + s * G_STAGE + a * G_TILE;
#pragma unroll
            for (int i = 0; i < 4; i++) {
                int idx = tid + i * 256;
                int rr = idx >> 3, cc = idx & 7;
                cp16(dstb + rr * G_RSB + cc * 16,
                     g + (size_t)(rbase + rr) * K + k0 + cc * 8);
            }
        }
        cp_commit();
    };

    issue(0, 0);
    issue(1, 1);

    for (int kt = 0; kt < KT; kt++) {
        if (kt == KT - 1) cp_wait<0>(); else cp_wait<1>();
        __syncthreads();
        const char* st = smem + (kt & 1) * G_STAGE;
        const uint32_t* A32  = (const uint32_t*)(st);
        const uint32_t* B32h = (const uint32_t*)(st + G_TILE);
        const uint32_t* B32l = (const uint32_t*)(st + 2 * G_TILE);

#pragma unroll
        for (int kk = 0; kk < 4; kk++) {
            uint32_t ah[4][4], bh[4][2], bl[4][2];
#pragma unroll
            for (int mt = 0; mt < 4; mt++) {
                int row = wm * 64 + mt * 16 + r;
                int w0 = row * 36 + kk * 8 + c;
                ah[mt][0] = A32[w0];     ah[mt][1] = A32[w0 + 288];
                ah[mt][2] = A32[w0 + 4]; ah[mt][3] = A32[w0 + 292];
            }
#pragma unroll
            for (int nt = 0; nt < 4; nt++) {
                int rn = wn * 32 + nt * 8 + r;
                int w0 = rn * 36 + kk * 8 + c;
                bh[nt][0] = B32h[w0]; bh[nt][1] = B32h[w0 + 4];
                bl[nt][0] = B32l[w0]; bl[nt][1] = B32l[w0 + 4];
            }
#pragma unroll
            for (int mt = 0; mt < 4; mt++)
#pragma unroll
                for (int nt = 0; nt < 4; nt++) {
                    mma16816(acc[mt][nt], ah[mt], bh[nt]);
                    mma16816(acc[mt][nt], ah[mt], bl[nt]);
                }
        }
        __syncthreads();
        if (kt + 2 < KT) issue(kt + 2, kt & 1);
    }

#pragma unroll
    for (int mt = 0; mt < 4; mt++) {
#pragma unroll
        for (int nt = 0; nt < 4; nt++) {
            int row = m0 + wm * 64 + mt * 16 + r;
            int col = n0 + wn * 32 + nt * 8 + 2 * c;
            float b0 = bias[col], b1 = bias[col + 1];
            float f0 = acc[mt][nt][0] + b0, f1 = acc[mt][nt][1] + b1;
            float f2 = acc[mt][nt][2] + b0, f3 = acc[mt][nt][3] + b1;
            if (OUT == 0) {
                *(float2*)&Cf[(size_t)row * N + col]       = make_float2(f0, f1);
                *(float2*)&Cf[(size_t)(row + 8) * N + col] = make_float2(f2, f3);
            } else {
                *(uint32_t*)&Ch[(size_t)row * N + col]       = packh2(f0, f1);
                *(uint32_t*)&Ch[(size_t)(row + 8) * N + col] = packh2(f2, f3);
            }
        }
    }
}

// ---------------------------------------------------------------------------
// V transpose: g_V fp32 [tok][DM] -> fp16 single [b][h][d][s]
// ---------------------------------------------------------------------------
__global__ __launch_bounds__(256)
void vtrans()
{
    __shared__ float sm[64][65];
    const int tid = threadIdx.x;
    const int s0 = blockIdx.x * 64, h = blockIdx.y, b = blockIdx.z;
#pragma unroll
    for (int i = 0; i < 16; i++) {
        int lin = tid + i * 256;
        int rr = lin >> 6, d = lin & 63;
        sm[rr][d] = g_V[(size_t)(b * SEQ + s0 + rr) * DM + h * 64 + d];
    }
    __syncthreads();
#pragma unroll
    for (int i = 0; i < 16; i++) {
        int lin = tid + i * 256;
        int dd = lin >> 6, ss = lin & 63;
        size_t o = ((size_t)((b * NH + h) * 64 + dd)) * SEQ + s0 + ss;
        g_vt[o] = __float2half_rn(sm[ss][dd]);
    }
}

// ---------------------------------------------------------------------------
// zdenom: Z = 1/sum_h e_h; stores e_h (fp16) to g_E[b][h][q][k]
// Q fp16, K fp16 single: ONE MMA per fragment pair.
// ---------------------------------------------------------------------------
namespace {
constexpr int Z_QT    = 18432;                 // Q tile 128 x 144B
constexpr int Z_KT    = 9216;                  // K tile 64 x 144B
constexpr int Z_STAGE = Z_QT + Z_KT;           // 27648
constexpr int Z_SMEM  = 2 * Z_STAGE;           // 55296
}

__global__ __launch_bounds__(256)
void zdenom_mma()
{
    extern __shared__ __align__(16) char smem[];
    const uint32_t sb = smem_u32(smem);
    const int tid = threadIdx.x, lane = tid & 31, wid = tid >> 5;
    const int r = lane >> 2, c = lane & 3;
    const int b = blockIdx.z, q0 = blockIdx.y * 128, k0 = blockIdx.x * 64;

    auto issue = [&](int h, int s) {
        const uint32_t base = sb + s * Z_STAGE;
#pragma unroll
        for (int i = 0; i < 4; i++) {          // Q: 128 rows x 8 chunks
            int idx = tid + i * 256;
            int rr = idx >> 3, cc = idx & 7;
            cp16(base + rr * 144 + cc * 16,
                 g_q + (size_t)(b * SEQ + q0 + rr) * DM + h * 64 + cc * 8);
        }
#pragma unroll
        for (int i = 0; i < 2; i++) {          // K: 64 rows x 8 chunks
            int idx = tid + i * 256;
            int rr = idx >> 3, cc = idx & 7;
            cp16(base + Z_QT + rr * 144 + cc * 16,
                 g_k + (size_t)(b * SEQ + k0 + rr) * DM + h * 64 + cc * 8);
        }
        cp_commit();
    };

    issue(0, 0);
    issue(1, 1);

    float z[8][4];
#pragma unroll
    for (int i = 0; i < 8; i++)
#pragma unroll
        for (int j = 0; j < 4; j++) z[i][j] = 0.f;

    for (int h = 0; h < NH; h++) {
        if (h == NH - 1) cp_wait<0>(); else cp_wait<1>();
        __syncthreads();
        const char* st = smem + (h & 1) * Z_STAGE;
        const uint32_t* Q32 = (const uint32_t*)(st);
        const uint32_t* K32 = (const uint32_t*)(st + Z_QT);

        float sc[8][4];
#pragma unroll
        for (int i = 0; i < 8; i++)
#pragma unroll
            for (int j = 0; j < 4; j++) sc[i][j] = 0.f;

#pragma unroll
        for (int kk = 0; kk < 4; kk++) {
            uint32_t aq[4];
            {
                int row = wid * 16 + r;
                int w0 = row * 36 + kk * 8 + c;
                aq[0] = Q32[w0];     aq[1] = Q32[w0 + 288];
                aq[2] = Q32[w0 + 4]; aq[3] = Q32[w0 + 292];
            }
#pragma unroll
            for (int nt = 0; nt < 8; nt++) {
                uint32_t bk[2];
                int rn = nt * 8 + r;
                int w0 = rn * 36 + kk * 8 + c;
                bk[0] = K32[w0]; bk[1] = K32[w0 + 4];
                mma16816(sc[nt], aq, bk);
            }
        }

#pragma unroll
        for (int i = 0; i < 8; i++)
#pragma unroll
            for (int j = 0; j < 4; j++) {
                sc[i][j] = ex2(sc[i][j] * SCLOG2E);
                z[i][j] += sc[i][j];
            }
        {
            size_t eb = ((size_t)((b * NH + h) * SEQ) + q0 + wid * 16 + r) * SEQ + k0;
#pragma unroll
            for (int nt = 0; nt < 8; nt++) {
                *(uint32_t*)&g_E[eb + nt * 8 + 2 * c] = packh2(sc[nt][0], sc[nt][1]);
                *(uint32_t*)&g_E[eb + (size_t)8 * SEQ + nt * 8 + 2 * c] =
                    packh2(sc[nt][2], sc[nt][3]);
            }
        }

        __syncthreads();
        if (h + 2 < NH) issue(h + 2, h & 1);
    }

#pragma unroll
    for (int nt = 0; nt < 8; nt++) {
        int q = q0 + wid * 16 + r;
        int col = k0 + nt * 8 + 2 * c;
        *(float2*)&g_Z[(size_t)(b * SEQ + q) * SEQ + col] =
            make_float2(frcp(z[nt][0]), frcp(z[nt][1]));
        *(float2*)&g_Z[(size_t)(b * SEQ + q + 8) * SEQ + col] =
            make_float2(frcp(z[nt][2]), frcp(z[nt][3]));
    }
}

// ---------------------------------------------------------------------------
// attn (PV only): p = E .* rz (half2 mul); acc += p @ V (single fp16 V)
// ---------------------------------------------------------------------------
namespace {
constexpr int AE_T    = 18432;                 // E tile 128 x 144B
constexpr int AV_T    = 9216;                  // V tile 64 x 144B
constexpr int A_STAGE = AE_T + AV_T;           // 27648
constexpr int A_SMEM  = 2 * A_STAGE;           // 55296
}

__global__ __launch_bounds__(256)
void attn_mma()
{
    extern __shared__ __align__(16) char smem[];
    const uint32_t sb = smem_u32(smem);
    const int tid = threadIdx.x, lane = tid & 31, wid = tid >> 5;
    const int r = lane >> 2, c = lane & 3;
    const int b = blockIdx.z, h = blockIdx.y, q0 = blockIdx.x * 128;
    const int hc = h * 64;
    const __half* Eb = g_E + (size_t)(b * NH + h) * SEQ * SEQ;

    auto issue = [&](int kt, int s) {
        const uint32_t base = sb + s * A_STAGE;
#pragma unroll
        for (int i = 0; i < 4; i++) {        // E: 128 rows x 8 chunks
            int idx = tid + i * 256;
            int rr = idx >> 3, cc = idx & 7;
            cp16(base + rr * 144 + cc * 16,
                 Eb + (size_t)(q0 + rr) * SEQ + kt * 64 + cc * 8);
        }
#pragma unroll
        for (int i = 0; i < 2; i++) {        // V: 64 rows x 8 chunks
            int idx = tid + i * 256;
            int r2 = idx >> 3, cc = idx & 7;
            cp16(base + AE_T + r2 * 144 + cc * 16,
                 g_vt + (size_t)((b * NH + h) * 64 + r2) * SEQ + kt * 64 + cc * 8);
        }
        cp_commit();
    };

    issue(0, 0);
    issue(1, 1);

    float acc[8][4];
#pragma unroll
    for (int i = 0; i < 8; i++)
#pragma unroll
        for (int j = 0; j < 4; j++) acc[i][j] = 0.f;

    const int KT = SEQ / 64;   // 32
    for (int kt = 0; kt < KT; kt++) {
        // rz for this tile, packed to half2: [kk][pos]; pos 0=(row,k),1=(row,k+8),
        // 2=(row+8,k),3=(row+8,k+8)
        uint32_t rzh[4][4];
        {
            const float* Z0 = g_Z + (size_t)(b * SEQ + q0 + wid * 16 + r) * SEQ
                              + kt * 64 + 2 * c;
            const float* Z1 = Z0 + (size_t)8 * SEQ;
#pragma unroll
            for (int kk = 0; kk < 4; kk++) {
                float2 a0 = *(const float2*)(Z0 + kk * 16);
                float2 a1 = *(const float2*)(Z0 + kk * 16 + 8);
                float2 a2 = *(const float2*)(Z1 + kk * 16);
                float2 a3 = *(const float2*)(Z1 + kk * 16 + 8);
                rzh[kk][0] = packh2(a0.x, a0.y);
                rzh[kk][1] = packh2(a1.x, a1.y);
                rzh[kk][2] = packh2(a2.x, a2.y);
                rzh[kk][3] = packh2(a3.x, a3.y);
            }
        }
        if (kt == KT - 1) cp_wait<0>(); else cp_wait<1>();
        __syncthreads();
        const char* st = smem + (kt & 1) * A_STAGE;
        const uint32_t* E32 = (const uint32_t*)(st);
        const uint32_t* V32 = (const uint32_t*)(st + AE_T);

#pragma unroll
        for (int kk = 0; kk < 4; kk++) {
            uint32_t ap[4];
            {
                int w0 = (wid * 16 + r) * 36 + kk * 8 + c;
                ap[0] = hmul2u(E32[w0],       rzh[kk][0]);   // (row,   k)
                ap[1] = hmul2u(E32[w0 + 288], rzh[kk][2]);   // (row+8, k)
                ap[2] = hmul2u(E32[w0 + 4],   rzh[kk][1]);   // (row,   k+8)
                ap[3] = hmul2u(E32[w0 + 292], rzh[kk][3]);   // (row+8, k+8)
            }
#pragma unroll
            for (int dt = 0; dt < 8; dt++) {
                uint32_t bv[2];
                int w1 = (dt * 8 + r) * 36 + kk * 8 + c;
                bv[0] = V32[w1]; bv[1] = V32[w1 + 4];
                mma16816(acc[dt], ap, bv);
            }
        }
        __syncthreads();
        if (kt + 2 < KT) issue(kt + 2, kt & 1);
    }

    // epilogue: context -> fp16 single
#pragma unroll
    for (int dt = 0; dt < 8; dt++) {
        int row = b * SEQ + q0 + wid * 16 + r;
        int col = hc + dt * 8 + 2 * c;
        *(uint32_t*)&g_c[(size_t)row * DM + col]       = packh2(acc[dt][0], acc[dt][1]);
        *(uint32_t*)&g_c[(size_t)(row + 8) * DM + col] = packh2(acc[dt][2], acc[dt][3]);
    }
}

// ---------------------------------------------------------------------------
extern "C" void kernel_launch(void* const* d_in, const int* in_sizes, int n_in,
                              void* d_out, int out_size)
{
    (void)in_sizes; (void)n_in; (void)out_size;
    const float* x  = (const float*)d_in[0];
    const float* Wq = (const float*)d_in[1];
    const float* bq = (const float*)d_in[2];
    const float* Wk = (const float*)d_in[3];
    const float* bk = (const float*)d_in[4];
    const float* Wv = (const float*)d_in[5];
    const float* bv = (const float*)d_in[6];
    const float* Wo = (const float*)d_in[7];
    const float* bo = (const float*)d_in[8];
    float* out = (float*)d_out;

    __half *xp, *wh, *wl, *qp, *kp, *cp;
    float* Vp;
    cudaGetSymbolAddress((void**)&xp, g_x);
    cudaGetSymbolAddress((void**)&wh, g_wh);
    cudaGetSymbolAddress((void**)&wl, g_wl);
    cudaGetSymbolAddress((void**)&qp, g_q);
    cudaGetSymbolAddress((void**)&kp, g_k);
    cudaGetSymbolAddress((void**)&cp, g_c);
    cudaGetSymbolAddress((void**)&Vp, g_V);

    cudaFuncSetAttribute(gemm_mma<0>, cudaFuncAttributeMaxDynamicSharedMemorySize, G_SMEM);
    cudaFuncSetAttribute(gemm_mma<1>, cudaFuncAttributeMaxDynamicSharedMemorySize, G_SMEM);
    cudaFuncSetAttribute(zdenom_mma,  cudaFuncAttributeMaxDynamicSharedMemorySize, Z_SMEM);
    cudaFuncSetAttribute(attn_mma,    cudaFuncAttributeMaxDynamicSharedMemorySize, A_SMEM);

    const int NX = NTOK * DM;   // 4M
    const int NW = DM * DM;     // 1M
    cvt_h<<<NX / 1024, 256>>>(x, xp, NX);
    cvt_w4<<<dim3(NW / 1024, 4), 256>>>(Wq, Wk, Wv, Wo, wh, wl);

    dim3 gproj(DM / 128, NTOK / 128);   // (8, 32)
    gemm_mma<1><<<gproj, 256, G_SMEM>>>(xp, wh + 0 * NW, wl + 0 * NW, bq,
                                        nullptr, qp, NTOK, DM, DM);
    gemm_mma<1><<<gproj, 256, G_SMEM>>>(xp, wh + 1 * NW, wl + 1 * NW, bk,
                                        nullptr, kp, NTOK, DM, DM);
    gemm_mma<0><<<gproj, 256, G_SMEM>>>(xp, wh + 2 * NW, wl + 2 * NW, bv,
                                        Vp, nullptr, NTOK, DM, DM);

    zdenom_mma<<<dim3(SEQ / 64, SEQ / 128, BT), 256, Z_SMEM>>>();

    vtrans<<<dim3(SEQ / 64, NH, BT), 256>>>();

    attn_mma<<<dim3(SEQ / 128, NH, BT), 256, A_SMEM>>>();

    gemm_mma<0><<<gproj, 256, G_SMEM>>>(cp, wh + 3 * NW, wl + 3 * NW, bo,
                                        out, nullptr, NTOK, DM, DM);
}

// round 10
// speedup vs baseline: 1.0008x; 1.0008x over previous
#include <cuda_runtime.h>
#include <cuda_bf16.h>
#include <cuda_fp16.h>
#include <cstdint>

namespace {
constexpr int SEQ = 2048;
constexpr int BT  = 2;
constexpr int DM  = 1024;
constexpr int NH  = 16;
constexpr int NTOK = BT * SEQ;     // 4096
constexpr float SCLOG2E = 0.125f * 1.4426950408889634f;  // scale * log2(e)
}

// ---------------- device scratch (allocation-free) ----------------
__device__ __half g_q [NTOK * DM];                   // Q, fp16 single
__device__ __half g_k [NTOK * DM];                   // K, fp16 single
__device__ float  g_V [NTOK * DM];
__device__ __half g_vt[NTOK * DM];                   // [b][h][d][s], fp16 single
__device__ __half g_c [NTOK * DM];                   // context, fp16 single
__device__ float  g_Z [BT * SEQ * SEQ];              // reciprocal denom
__device__ __half g_E [(size_t)BT * NH * SEQ * SEQ]; // exp(scores), [b][h][q][k]
__device__ __half g_x [NTOK * DM];                   // x, fp16 single
__device__ __half g_wh[4][DM * DM], g_wl[4][DM * DM];

// ---------------- tiny PTX helpers (sm_103-safe) ----------------
__device__ __forceinline__ uint32_t smem_u32(const void* p) {
    uint32_t a;
    asm("{ .reg .u64 t; cvta.to.shared.u64 t, %1; cvt.u32.u64 %0, t; }" : "=r"(a) : "l"(p));
    return a;
}
__device__ __forceinline__ void cp16(uint32_t dst, const void* src) {
    asm volatile("cp.async.cg.shared.global [%0], [%1], 16;" :: "r"(dst), "l"(src) : "memory");
}
__device__ __forceinline__ void cp_commit() {
    asm volatile("cp.async.commit_group;" ::: "memory");
}
template <int N> __device__ __forceinline__ void cp_wait() {
    asm volatile("cp.async.wait_group %0;" :: "n"(N) : "memory");
}
__device__ __forceinline__ void mma16816(float* d, const uint32_t* a, const uint32_t* b) {
    asm volatile(
        "mma.sync.aligned.m16n8k16.row.col.f32.f16.f16.f32 "
        "{%0,%1,%2,%3}, {%4,%5,%6,%7}, {%8,%9}, {%0,%1,%2,%3};"
        : "+f"(d[0]), "+f"(d[1]), "+f"(d[2]), "+f"(d[3])
        : "r"(a[0]), "r"(a[1]), "r"(a[2]), "r"(a[3]), "r"(b[0]), "r"(b[1]));
}
__device__ __forceinline__ float ex2(float x) {
    float y; asm("ex2.approx.ftz.f32 %0, %1;" : "=f"(y) : "f"(x)); return y;
}
__device__ __forceinline__ float frcp(float x) {
    float y; asm("rcp.approx.ftz.f32 %0, %1;" : "=f"(y) : "f"(x)); return y;
}
// pack two fp32 -> f16x2 reg: low half = `lo` (lower column index)
__device__ __forceinline__ uint32_t packh2(float lo, float hi) {
    uint32_t r; asm("cvt.rn.f16x2.f32 %0, %1, %2;" : "=r"(r) : "f"(hi), "f"(lo)); return r;
}
__device__ __forceinline__ uint32_t hmul2u(uint32_t a, uint32_t b) {
    __half2 r = __hmul2(*(const __half2*)&a, *(const __half2*)&b);
    return *(uint32_t*)&r;
}
// split (x,y) into hi f16x2 and residual-lo f16x2
__device__ __forceinline__ void split2h(float x, float y, uint32_t& hi, uint32_t& lo) {
    __half hx = __float2half_rn(x), hy = __float2half_rn(y);
    float rx = x - __half2float(hx), ry = y - __half2float(hy);
    __half2 h2; h2.x = hx; h2.y = hy;
    hi = *(uint32_t*)&h2;
    lo = packh2(rx, ry);
}

// ---------------------------------------------------------------------------
// fp32 -> fp16 single (for x)
// ---------------------------------------------------------------------------
__global__ __launch_bounds__(256)
void cvt_h(const float* __restrict__ in, __half* __restrict__ out, int n)
{
    int i = (blockIdx.x * 256 + threadIdx.x) * 4;
    if (i >= n) return;
    float4 v = *(const float4*)(in + i);
    ushort4 o;
    o.x = __half_as_ushort(__float2half_rn(v.x));
    o.y = __half_as_ushort(__float2half_rn(v.y));
    o.z = __half_as_ushort(__float2half_rn(v.z));
    o.w = __half_as_ushort(__float2half_rn(v.w));
    *(ushort4*)((unsigned short*)out + i) = o;
}

// all 4 weights: fp32 -> split fp16 hi/lo
__global__ __launch_bounds__(256)
void cvt_w4(const float* __restrict__ W0, const float* __restrict__ W1,
            const float* __restrict__ W2, const float* __restrict__ W3,
            __half* __restrict__ hi, __half* __restrict__ lo)
{
    const int NW = DM * DM;
    const float* in = (blockIdx.y == 0) ? W0 : (blockIdx.y == 1) ? W1
                    : (blockIdx.y == 2) ? W2 : W3;
    int i = (blockIdx.x * 256 + threadIdx.x) * 4;
    size_t o = (size_t)blockIdx.y * NW + i;
    float4 v = *(const float4*)(in + i);
    float a[4] = {v.x, v.y, v.z, v.w};
    unsigned short hs[4], ls[4];
#pragma unroll
    for (int j = 0; j < 4; j++) {
        __half h = __float2half_rn(a[j]);
        float r = a[j] - __half2float(h);
        hs[j] = __half_as_ushort(h);
        ls[j] = __half_as_ushort(__float2half_rn(r));
    }
    *(ushort4*)((unsigned short*)hi + o) = make_ushort4(hs[0], hs[1], hs[2], hs[3]);
    *(ushort4*)((unsigned short*)lo + o) = make_ushort4(ls[0], ls[1], ls[2], ls[3]);
}

// ---------------------------------------------------------------------------
// HMMA 2-term split-fp16 GEMM: C = A * B^T + bias (A fp16; B = Bh + Bl)
// OUT: 0 = fp32 Cf, 1 = fp16 single Ch
// ---------------------------------------------------------------------------
namespace {
constexpr int G_RSB   = 144;
constexpr int G_TILE  = 128 * G_RSB;       // 18432
constexpr int G_STAGE = 3 * G_TILE;        // 55296 (A, Bh, Bl)
constexpr int G_SMEM  = 2 * G_STAGE;       // 110592
}

template <int OUT>
__global__ __launch_bounds__(256, 2)
void gemm_mma(const __half* __restrict__ A,
              const __half* __restrict__ Bh, const __half* __restrict__ Bl,
              const float* __restrict__ bias,
              float* __restrict__ Cf, __half* __restrict__ Ch,
              int M, int N, int K)
{
    extern __shared__ __align__(16) char smem[];
    const uint32_t sb = smem_u32(smem);
    const int tid = threadIdx.x, lane = tid & 31, wid = tid >> 5;
    const int wm = wid >> 2, wn = wid & 3;
    const int r = lane >> 2, c = lane & 3;
    const int m0 = blockIdx.y * 128, n0 = blockIdx.x * 128;
    const int KT = K / 64;

    float acc[4][4][4];
#pragma unroll
    for (int i = 0; i < 4; i++)
#pragma unroll
        for (int j = 0; j < 4; j++)
#pragma unroll
            for (int q = 0; q < 4; q++) acc[i][j][q] = 0.f;

    auto issue = [&](int kt, int s) {
        const int k0 = kt * 64;
#pragma unroll
        for (int a = 0; a < 3; a++) {
            const __half* g = (a == 0) ? A : (a == 1) ? Bh : Bl;
            const int rbase = (a == 0) ? m0 : n0;
            const uint32_t dstb = sb + s * G_STAGE + a * G_TILE;
#pragma unroll
            for (int i = 0; i < 4; i++) {
                int idx = tid + i * 256;
                int rr = idx >> 3, cc = idx & 7;
                cp16(dstb + rr * G_RSB + cc * 16,
                     g + (size_t)(rbase + rr) * K + k0 + cc * 8);
            }
        }
        cp_commit();
    };

    issue(0, 0);
    issue(1, 1);

    for (int kt = 0; kt < KT; kt++) {
        if (kt == KT - 1) cp_wait<0>(); else cp_wait<1>();
        __syncthreads();
        const char* st = smem + (kt & 1) * G_STAGE;
        const uint32_t* A32  = (const uint32_t*)(st);
        const uint32_t* B32h = (const uint32_t*)(st + G_TILE);
        const uint32_t* B32l = (const uint32_t*)(st + 2 * G_TILE);

#pragma unroll
        for (int kk = 0; kk < 4; kk++) {
            uint32_t ah[4][4], bh[4][2], bl[4][2];
#pragma unroll
            for (int mt = 0; mt < 4; mt++) {
                int row = wm * 64 + mt * 16 + r;
                int w0 = row * 36 + kk * 8 + c;
                ah[mt][0] = A32[w0];     ah[mt][1] = A32[w0 + 288];
                ah[mt][2] = A32[w0 + 4]; ah[mt][3] = A32[w0 + 292];
            }
#pragma unroll
            for (int nt = 0; nt < 4; nt++) {
                int rn = wn * 32 + nt * 8 + r;
                int w0 = rn * 36 + kk * 8 + c;
                bh[nt][0] = B32h[w0]; bh[nt][1] = B32h[w0 + 4];
                bl[nt][0] = B32l[w0]; bl[nt][1] = B32l[w0 + 4];
            }
#pragma unroll
            for (int mt = 0; mt < 4; mt++)
#pragma unroll
                for (int nt = 0; nt < 4; nt++) {
                    mma16816(acc[mt][nt], ah[mt], bh[nt]);
                    mma16816(acc[mt][nt], ah[mt], bl[nt]);
                }
        }
        __syncthreads();
        if (kt + 2 < KT) issue(kt + 2, kt & 1);
    }

#pragma unroll
    for (int mt = 0; mt < 4; mt++) {
#pragma unroll
        for (int nt = 0; nt < 4; nt++) {
            int row = m0 + wm * 64 + mt * 16 + r;
            int col = n0 + wn * 32 + nt * 8 + 2 * c;
            float b0 = bias[col], b1 = bias[col + 1];
            float f0 = acc[mt][nt][0] + b0, f1 = acc[mt][nt][1] + b1;
            float f2 = acc[mt][nt][2] + b0, f3 = acc[mt][nt][3] + b1;
            if (OUT == 0) {
                *(float2*)&Cf[(size_t)row * N + col]       = make_float2(f0, f1);
                *(float2*)&Cf[(size_t)(row + 8) * N + col] = make_float2(f2, f3);
            } else {
                *(uint32_t*)&Ch[(size_t)row * N + col]       = packh2(f0, f1);
                *(uint32_t*)&Ch[(size_t)(row + 8) * N + col] = packh2(f2, f3);
            }
        }
    }
}

// ---------------------------------------------------------------------------
// V transpose: g_V fp32 [tok][DM] -> fp16 single [b][h][d][s]
// ---------------------------------------------------------------------------
__global__ __launch_bounds__(256)
void vtrans()
{
    __shared__ float sm[64][65];
    const int tid = threadIdx.x;
    const int s0 = blockIdx.x * 64, h = blockIdx.y, b = blockIdx.z;
#pragma unroll
    for (int i = 0; i < 16; i++) {
        int lin = tid + i * 256;
        int rr = lin >> 6, d = lin & 63;
        sm[rr][d] = g_V[(size_t)(b * SEQ + s0 + rr) * DM + h * 64 + d];
    }
    __syncthreads();
#pragma unroll
    for (int i = 0; i < 16; i++) {
        int lin = tid + i * 256;
        int dd = lin >> 6, ss = lin & 63;
        size_t o = ((size_t)((b * NH + h) * 64 + dd)) * SEQ + s0 + ss;
        g_vt[o] = __float2half_rn(sm[ss][dd]);
    }
}

// ---------------------------------------------------------------------------
// zdenom: Z = 1/sum_h e_h; stores e_h (fp16) to g_E[b][h][q][k]
// Q fp16, K fp16 single: ONE MMA per fragment pair.
// ---------------------------------------------------------------------------
namespace {
constexpr int Z_QT    = 18432;                 // Q tile 128 x 144B
constexpr int Z_KT    = 9216;                  // K tile 64 x 144B
constexpr int Z_STAGE = Z_QT + Z_KT;           // 27648
constexpr int Z_SMEM  = 2 * Z_STAGE;           // 55296
}

__global__ __launch_bounds__(256)
void zdenom_mma()
{
    extern __shared__ __align__(16) char smem[];
    const uint32_t sb = smem_u32(smem);
    const int tid = threadIdx.x, lane = tid & 31, wid = tid >> 5;
    const int r = lane >> 2, c = lane & 3;
    const int b = blockIdx.z, q0 = blockIdx.y * 128, k0 = blockIdx.x * 64;

    auto issue = [&](int h, int s) {
        const uint32_t base = sb + s * Z_STAGE;
#pragma unroll
        for (int i = 0; i < 4; i++) {          // Q: 128 rows x 8 chunks
            int idx = tid + i * 256;
            int rr = idx >> 3, cc = idx & 7;
            cp16(base + rr * 144 + cc * 16,
                 g_q + (size_t)(b * SEQ + q0 + rr) * DM + h * 64 + cc * 8);
        }
#pragma unroll
        for (int i = 0; i < 2; i++) {          // K: 64 rows x 8 chunks
            int idx = tid + i * 256;
            int rr = idx >> 3, cc = idx & 7;
            cp16(base + Z_QT + rr * 144 + cc * 16,
                 g_k + (size_t)(b * SEQ + k0 + rr) * DM + h * 64 + cc * 8);
        }
        cp_commit();
    };

    issue(0, 0);
    issue(1, 1);

    float z[8][4];
#pragma unroll
    for (int i = 0; i < 8; i++)
#pragma unroll
        for (int j = 0; j < 4; j++) z[i][j] = 0.f;

    for (int h = 0; h < NH; h++) {
        if (h == NH - 1) cp_wait<0>(); else cp_wait<1>();
        __syncthreads();
        const char* st = smem + (h & 1) * Z_STAGE;
        const uint32_t* Q32 = (const uint32_t*)(st);
        const uint32_t* K32 = (const uint32_t*)(st + Z_QT);

        float sc[8][4];
#pragma unroll
        for (int i = 0; i < 8; i++)
#pragma unroll
            for (int j = 0; j < 4; j++) sc[i][j] = 0.f;

#pragma unroll
        for (int kk = 0; kk < 4; kk++) {
            uint32_t aq[4];
            {
                int row = wid * 16 + r;
                int w0 = row * 36 + kk * 8 + c;
                aq[0] = Q32[w0];     aq[1] = Q32[w0 + 288];
                aq[2] = Q32[w0 + 4]; aq[3] = Q32[w0 + 292];
            }
#pragma unroll
            for (int nt = 0; nt < 8; nt++) {
                uint32_t bk[2];
                int rn = nt * 8 + r;
                int w0 = rn * 36 + kk * 8 + c;
                bk[0] = K32[w0]; bk[1] = K32[w0 + 4];
                mma16816(sc[nt], aq, bk);
            }
        }

#pragma unroll
        for (int i = 0; i < 8; i++)
#pragma unroll
            for (int j = 0; j < 4; j++) {
                sc[i][j] = ex2(sc[i][j] * SCLOG2E);
                z[i][j] += sc[i][j];
            }
        {
            size_t eb = ((size_t)((b * NH + h) * SEQ) + q0 + wid * 16 + r) * SEQ + k0;
#pragma unroll
            for (int nt = 0; nt < 8; nt++) {
                *(uint32_t*)&g_E[eb + nt * 8 + 2 * c] = packh2(sc[nt][0], sc[nt][1]);
                *(uint32_t*)&g_E[eb + (size_t)8 * SEQ + nt * 8 + 2 * c] =
                    packh2(sc[nt][2], sc[nt][3]);
            }
        }

        __syncthreads();
        if (h + 2 < NH) issue(h + 2, h & 1);
    }

#pragma unroll
    for (int nt = 0; nt < 8; nt++) {
        int q = q0 + wid * 16 + r;
        int col = k0 + nt * 8 + 2 * c;
        *(float2*)&g_Z[(size_t)(b * SEQ + q) * SEQ + col] =
            make_float2(frcp(z[nt][0]), frcp(z[nt][1]));
        *(float2*)&g_Z[(size_t)(b * SEQ + q + 8) * SEQ + col] =
            make_float2(frcp(z[nt][2]), frcp(z[nt][3]));
    }
}

// ---------------------------------------------------------------------------
// attn (PV only): p = E .* rz (half2 mul); acc += p @ V (single fp16 V)
// ---------------------------------------------------------------------------
namespace {
constexpr int AE_T    = 18432;                 // E tile 128 x 144B
constexpr int AV_T    = 9216;                  // V tile 64 x 144B
constexpr int A_STAGE = AE_T + AV_T;           // 27648
constexpr int A_SMEM  = 2 * A_STAGE;           // 55296
}

__global__ __launch_bounds__(256)
void attn_mma()
{
    extern __shared__ __align__(16) char smem[];
    const uint32_t sb = smem_u32(smem);
    const int tid = threadIdx.x, lane = tid & 31, wid = tid >> 5;
    const int r = lane >> 2, c = lane & 3;
    const int b = blockIdx.z, h = blockIdx.y, q0 = blockIdx.x * 128;
    const int hc = h * 64;
    const __half* Eb = g_E + (size_t)(b * NH + h) * SEQ * SEQ;

    auto issue = [&](int kt, int s) {
        const uint32_t base = sb + s * A_STAGE;
#pragma unroll
        for (int i = 0; i < 4; i++) {        // E: 128 rows x 8 chunks
            int idx = tid + i * 256;
            int rr = idx >> 3, cc = idx & 7;
            cp16(base + rr * 144 + cc * 16,
                 Eb + (size_t)(q0 + rr) * SEQ + kt * 64 + cc * 8);
        }
#pragma unroll
        for (int i = 0; i < 2; i++) {        // V: 64 rows x 8 chunks
            int idx = tid + i * 256;
            int r2 = idx >> 3, cc = idx & 7;
            cp16(base + AE_T + r2 * 144 + cc * 16,
                 g_vt + (size_t)((b * NH + h) * 64 + r2) * SEQ + kt * 64 + cc * 8);
        }
        cp_commit();
    };

    issue(0, 0);
    issue(1, 1);

    float acc[8][4];
#pragma unroll
    for (int i = 0; i < 8; i++)
#pragma unroll
        for (int j = 0; j < 4; j++) acc[i][j] = 0.f;

    const int KT = SEQ / 64;   // 32
    for (int kt = 0; kt < KT; kt++) {
        // rz for this tile, packed to half2: [kk][pos]; pos 0=(row,k),1=(row,k+8),
        // 2=(row+8,k),3=(row+8,k+8)
        uint32_t rzh[4][4];
        {
            const float* Z0 = g_Z + (size_t)(b * SEQ + q0 + wid * 16 + r) * SEQ
                              + kt * 64 + 2 * c;
            const float* Z1 = Z0 + (size_t)8 * SEQ;
#pragma unroll
            for (int kk = 0; kk < 4; kk++) {
                float2 a0 = *(const float2*)(Z0 + kk * 16);
                float2 a1 = *(const float2*)(Z0 + kk * 16 + 8);
                float2 a2 = *(const float2*)(Z1 + kk * 16);
                float2 a3 = *(const float2*)(Z1 + kk * 16 + 8);
                rzh[kk][0] = packh2(a0.x, a0.y);
                rzh[kk][1] = packh2(a1.x, a1.y);
                rzh[kk][2] = packh2(a2.x, a2.y);
                rzh[kk][3] = packh2(a3.x, a3.y);
            }
        }
        if (kt == KT - 1) cp_wait<0>(); else cp_wait<1>();
        __syncthreads();
        const char* st = smem + (kt & 1) * A_STAGE;
        const uint32_t* E32 = (const uint32_t*)(st);
        const uint32_t* V32 = (const uint32_t*)(st + AE_T);

#pragma unroll
        for (int kk = 0; kk < 4; kk++) {
            uint32_t ap[4];
            {
                int w0 = (wid * 16 + r) * 36 + kk * 8 + c;
                ap[0] = hmul2u(E32[w0],       rzh[kk][0]);   // (row,   k)
                ap[1] = hmul2u(E32[w0 + 288], rzh[kk][2]);   // (row+8, k)
                ap[2] = hmul2u(E32[w0 + 4],   rzh[kk][1]);   // (row,   k+8)
                ap[3] = hmul2u(E32[w0 + 292], rzh[kk][3]);   // (row+8, k+8)
            }
#pragma unroll
            for (int dt = 0; dt < 8; dt++) {
                uint32_t bv[2];
                int w1 = (dt * 8 + r) * 36 + kk * 8 + c;
                bv[0] = V32[w1]; bv[1] = V32[w1 + 4];
                mma16816(acc[dt], ap, bv);
            }
        }
        __syncthreads();
        if (kt + 2 < KT) issue(kt + 2, kt & 1);
    }

    // epilogue: context -> fp16 single
#pragma unroll
    for (int dt = 0; dt < 8; dt++) {
        int row = b * SEQ + q0 + wid * 16 + r;
        int col = hc + dt * 8 + 2 * c;
        *(uint32_t*)&g_c[(size_t)row * DM + col]       = packh2(acc[dt][0], acc[dt][1]);
        *(uint32_t*)&g_c[(size_t)(row + 8) * DM + col] = packh2(acc[dt][2], acc[dt][3]);
    }
}

// ---------------------------------------------------------------------------
extern "C" void kernel_launch(void* const* d_in, const int* in_sizes, int n_in,
                              void* d_out, int out_size)
{
    (void)in_sizes; (void)n_in; (void)out_size;
    const float* x  = (const float*)d_in[0];
    const float* Wq = (const float*)d_in[1];
    const float* bq = (const float*)d_in[2];
    const float* Wk = (const float*)d_in[3];
    const float* bk = (const float*)d_in[4];
    const float* Wv = (const float*)d_in[5];
    const float* bv = (const float*)d_in[6];
    const float* Wo = (const float*)d_in[7];
    const float* bo = (const float*)d_in[8];
    float* out = (float*)d_out;

    __half *xp, *wh, *wl, *qp, *kp, *cp;
    float* Vp;
    cudaGetSymbolAddress((void**)&xp, g_x);
    cudaGetSymbolAddress((void**)&wh, g_wh);
    cudaGetSymbolAddress((void**)&wl, g_wl);
    cudaGetSymbolAddress((void**)&qp, g_q);
    cudaGetSymbolAddress((void**)&kp, g_k);
    cudaGetSymbolAddress((void**)&cp, g_c);
    cudaGetSymbolAddress((void**)&Vp, g_V);

    cudaFuncSetAttribute(gemm_mma<0>, cudaFuncAttributeMaxDynamicSharedMemorySize, G_SMEM);
    cudaFuncSetAttribute(gemm_mma<1>, cudaFuncAttributeMaxDynamicSharedMemorySize, G_SMEM);
    cudaFuncSetAttribute(zdenom_mma,  cudaFuncAttributeMaxDynamicSharedMemorySize, Z_SMEM);
    cudaFuncSetAttribute(attn_mma,    cudaFuncAttributeMaxDynamicSharedMemorySize, A_SMEM);

    const int NX = NTOK * DM;   // 4M
    const int NW = DM * DM;     // 1M
    cvt_h<<<NX / 1024, 256>>>(x, xp, NX);
    cvt_w4<<<dim3(NW / 1024, 4), 256>>>(Wq, Wk, Wv, Wo, wh, wl);

    dim3 gproj(DM / 128, NTOK / 128);   // (8, 32)
    gemm_mma<1><<<gproj, 256, G_SMEM>>>(xp, wh + 0 * NW, wl + 0 * NW, bq,
                                        nullptr, qp, NTOK, DM, DM);
    gemm_mma<1><<<gproj, 256, G_SMEM>>>(xp, wh + 1 * NW, wl + 1 * NW, bk,
                                        nullptr, kp, NTOK, DM, DM);
    gemm_mma<0><<<gproj, 256, G_SMEM>>>(xp, wh + 2 * NW, wl + 2 * NW, bv,
                                        Vp, nullptr, NTOK, DM, DM);

    zdenom_mma<<<dim3(SEQ / 64, SEQ / 128, BT), 256, Z_SMEM>>>();

    vtrans<<<dim3(SEQ / 64, NH, BT), 256>>>();

    attn_mma<<<dim3(SEQ / 128, NH, BT), 256, A_SMEM>>>();

    gemm_mma<0><<<gproj, 256, G_SMEM>>>(cp, wh + 3 * NW, wl + 3 * NW, bo,
                                        out, nullptr, NTOK, DM, DM);
}

// round 11
// speedup vs baseline: 1.4878x; 1.4866x over previous
#include <cuda_runtime.h>
#include <cuda_bf16.h>
#include <cuda_fp16.h>
#include <cstdint>

namespace {
constexpr int SEQ = 2048;
constexpr int BT  = 2;
constexpr int DM  = 1024;
constexpr int NH  = 16;
constexpr int NTOK = BT * SEQ;     // 4096
constexpr float SCLOG2E = 0.125f * 1.4426950408889634f;  // scale * log2(e)
}

// ---------------- device scratch (allocation-free) ----------------
__device__ __half g_q [NTOK * DM];                   // Q, fp16 single
__device__ __half g_k [NTOK * DM];                   // K, fp16 single
__device__ float  g_V [NTOK * DM];
__device__ __half g_vt[NTOK * DM];                   // [b][h][d][s], fp16 single
__device__ __half g_c [NTOK * DM];                   // context, fp16 single
__device__ float  g_Z [BT * SEQ * SEQ];              // reciprocal denom
__device__ __half g_E [(size_t)BT * NH * SEQ * SEQ]; // exp(scores), [b][h][q][k]
__device__ __half g_x [NTOK * DM];                   // x, fp16 single
__device__ __half g_wh[4][DM * DM], g_wl[4][DM * DM];

// ---------------- tiny PTX helpers (sm_103-safe) ----------------
__device__ __forceinline__ uint32_t smem_u32(const void* p) {
    uint32_t a;
    asm("{ .reg .u64 t; cvta.to.shared.u64 t, %1; cvt.u32.u64 %0, t; }" : "=r"(a) : "l"(p));
    return a;
}
__device__ __forceinline__ void cp16(uint32_t dst, const void* src) {
    asm volatile("cp.async.cg.shared.global [%0], [%1], 16;" :: "r"(dst), "l"(src) : "memory");
}
__device__ __forceinline__ void cp_commit() {
    asm volatile("cp.async.commit_group;" ::: "memory");
}
template <int N> __device__ __forceinline__ void cp_wait() {
    asm volatile("cp.async.wait_group %0;" :: "n"(N) : "memory");
}
__device__ __forceinline__ void mma16816(float* d, const uint32_t* a, const uint32_t* b) {
    asm volatile(
        "mma.sync.aligned.m16n8k16.row.col.f32.f16.f16.f32 "
        "{%0,%1,%2,%3}, {%4,%5,%6,%7}, {%8,%9}, {%0,%1,%2,%3};"
        : "+f"(d[0]), "+f"(d[1]), "+f"(d[2]), "+f"(d[3])
        : "r"(a[0]), "r"(a[1]), "r"(a[2]), "r"(a[3]), "r"(b[0]), "r"(b[1]));
}
__device__ __forceinline__ float ex2(float x) {
    float y; asm("ex2.approx.ftz.f32 %0, %1;" : "=f"(y) : "f"(x)); return y;
}
__device__ __forceinline__ float frcp(float x) {
    float y; asm("rcp.approx.ftz.f32 %0, %1;" : "=f"(y) : "f"(x)); return y;
}
// pack two fp32 -> f16x2 reg: low half = `lo` (lower column index)
__device__ __forceinline__ uint32_t packh2(float lo, float hi) {
    uint32_t r; asm("cvt.rn.f16x2.f32 %0, %1, %2;" : "=r"(r) : "f"(hi), "f"(lo)); return r;
}
__device__ __forceinline__ uint32_t hmul2u(uint32_t a, uint32_t b) {
    __half2 r = __hmul2(*(const __half2*)&a, *(const __half2*)&b);
    return *(uint32_t*)&r;
}
// split (x,y) into hi f16x2 and residual-lo f16x2
__device__ __forceinline__ void split2h(float x, float y, uint32_t& hi, uint32_t& lo) {
    __half hx = __float2half_rn(x), hy = __float2half_rn(y);
    float rx = x - __half2float(hx), ry = y - __half2float(hy);
    __half2 h2; h2.x = hx; h2.y = hy;
    hi = *(uint32_t*)&h2;
    lo = packh2(rx, ry);
}

// ---------------------------------------------------------------------------
// fp32 -> fp16 single (for x)
// ---------------------------------------------------------------------------
__global__ __launch_bounds__(256)
void cvt_h(const float* __restrict__ in, __half* __restrict__ out, int n)
{
    int i = (blockIdx.x * 256 + threadIdx.x) * 4;
    if (i >= n) return;
    float4 v = *(const float4*)(in + i);
    ushort4 o;
    o.x = __half_as_ushort(__float2half_rn(v.x));
    o.y = __half_as_ushort(__float2half_rn(v.y));
    o.z = __half_as_ushort(__float2half_rn(v.z));
    o.w = __half_as_ushort(__float2half_rn(v.w));
    *(ushort4*)((unsigned short*)out + i) = o;
}

// all 4 weights: fp32 -> split fp16 hi/lo
__global__ __launch_bounds__(256)
void cvt_w4(const float* __restrict__ W0, const float* __restrict__ W1,
            const float* __restrict__ W2, const float* __restrict__ W3,
            __half* __restrict__ hi, __half* __restrict__ lo)
{
    const int NW = DM * DM;
    const float* in = (blockIdx.y == 0) ? W0 : (blockIdx.y == 1) ? W1
                    : (blockIdx.y == 2) ? W2 : W3;
    int i = (blockIdx.x * 256 + threadIdx.x) * 4;
    size_t o = (size_t)blockIdx.y * NW + i;
    float4 v = *(const float4*)(in + i);
    float a[4] = {v.x, v.y, v.z, v.w};
    unsigned short hs[4], ls[4];
#pragma unroll
    for (int j = 0; j < 4; j++) {
        __half h = __float2half_rn(a[j]);
        float r = a[j] - __half2float(h);
        hs[j] = __half_as_ushort(h);
        ls[j] = __half_as_ushort(__float2half_rn(r));
    }
    *(ushort4*)((unsigned short*)hi + o) = make_ushort4(hs[0], hs[1], hs[2], hs[3]);
    *(ushort4*)((unsigned short*)lo + o) = make_ushort4(ls[0], ls[1], ls[2], ls[3]);
}

// ---------------------------------------------------------------------------
// HMMA 2-term split-fp16 GEMM: C = A * B^T + bias (A fp16; B = Bh + Bl)
// OUT: 0 = fp32 Cf, 1 = fp16 single Ch
// ---------------------------------------------------------------------------
namespace {
constexpr int G_RSB   = 144;
constexpr int G_TILE  = 128 * G_RSB;       // 18432
constexpr int G_STAGE = 3 * G_TILE;        // 55296 (A, Bh, Bl)
constexpr int G_SMEM  = 2 * G_STAGE;       // 110592
}

template <int OUT>
__global__ __launch_bounds__(256, 2)
void gemm_mma(const __half* __restrict__ A,
              const __half* __restrict__ Bh, const __half* __restrict__ Bl,
              const float* __restrict__ bias,
              float* __restrict__ Cf, __half* __restrict__ Ch,
              int M, int N, int K)
{
    extern __shared__ __align__(16) char smem[];
    const uint32_t sb = smem_u32(smem);
    const int tid = threadIdx.x, lane = tid & 31, wid = tid >> 5;
    const int wm = wid >> 2, wn = wid & 3;
    const int r = lane >> 2, c = lane & 3;
    const int m0 = blockIdx.y * 128, n0 = blockIdx.x * 128;
    const int KT = K / 64;

    float acc[4][4][4];
#pragma unroll
    for (int i = 0; i < 4; i++)
#pragma unroll
        for (int j = 0; j < 4; j++)
#pragma unroll
            for (int q = 0; q < 4; q++) acc[i][j][q] = 0.f;

    auto issue = [&](int kt, int s) {
        const int k0 = kt * 64;
#pragma unroll
        for (int a = 0; a < 3; a++) {
            const __half* g = (a == 0) ? A : (a == 1) ? Bh : Bl;
            const int rbase = (a == 0) ? m0 : n0;
            const uint32_t dstb = sb + s * G_STAGE + a * G_TILE;
#pragma unroll
            for (int i = 0; i < 4; i++) {
                int idx = tid + i * 256;
                int rr = idx >> 3, cc = idx & 7;
                cp16(dstb + rr * G_RSB + cc * 16,
                     g + (size_t)(rbase + rr) * K + k0 + cc * 8);
            }
        }
        cp_commit();
    };

    issue(0, 0);
    issue(1, 1);

    for (int kt = 0; kt < KT; kt++) {
        if (kt == KT - 1) cp_wait<0>(); else cp_wait<1>();
        __syncthreads();
        const char* st = smem + (kt & 1) * G_STAGE;
        const uint32_t* A32  = (const uint32_t*)(st);
        const uint32_t* B32h = (const uint32_t*)(st + G_TILE);
        const uint32_t* B32l = (const uint32_t*)(st + 2 * G_TILE);

#pragma unroll
        for (int kk = 0; kk < 4; kk++) {
            uint32_t ah[4][4], bh[4][2], bl[4][2];
#pragma unroll
            for (int mt = 0; mt < 4; mt++) {
                int row = wm * 64 + mt * 16 + r;
                int w0 = row * 36 + kk * 8 + c;
                ah[mt][0] = A32[w0];     ah[mt][1] = A32[w0 + 288];
                ah[mt][2] = A32[w0 + 4]; ah[mt][3] = A32[w0 + 292];
            }
#pragma unroll
            for (int nt = 0; nt < 4; nt++) {
                int rn = wn * 32 + nt * 8 + r;
                int w0 = rn * 36 + kk * 8 + c;
                bh[nt][0] = B32h[w0]; bh[nt][1] = B32h[w0 + 4];
                bl[nt][0] = B32l[w0]; bl[nt][1] = B32l[w0 + 4];
            }
#pragma unroll
            for (int mt = 0; mt < 4; mt++)
#pragma unroll
                for (int nt = 0; nt < 4; nt++) {
                    mma16816(acc[mt][nt], ah[mt], bh[nt]);
                    mma16816(acc[mt][nt], ah[mt], bl[nt]);
                }
        }
        __syncthreads();
        if (kt + 2 < KT) issue(kt + 2, kt & 1);
    }

#pragma unroll
    for (int mt = 0; mt < 4; mt++) {
#pragma unroll
        for (int nt = 0; nt < 4; nt++) {
            int row = m0 + wm * 64 + mt * 16 + r;
            int col = n0 + wn * 32 + nt * 8 + 2 * c;
            float b0 = bias[col], b1 = bias[col + 1];
            float f0 = acc[mt][nt][0] + b0, f1 = acc[mt][nt][1] + b1;
            float f2 = acc[mt][nt][2] + b0, f3 = acc[mt][nt][3] + b1;
            if (OUT == 0) {
                *(float2*)&Cf[(size_t)row * N + col]       = make_float2(f0, f1);
                *(float2*)&Cf[(size_t)(row + 8) * N + col] = make_float2(f2, f3);
            } else {
                *(uint32_t*)&Ch[(size_t)row * N + col]       = packh2(f0, f1);
                *(uint32_t*)&Ch[(size_t)(row + 8) * N + col] = packh2(f2, f3);
            }
        }
    }
}

// ---------------------------------------------------------------------------
// V transpose: g_V fp32 [tok][DM] -> fp16 single [b][h][d][s]
// ---------------------------------------------------------------------------
__global__ __launch_bounds__(256)
void vtrans()
{
    __shared__ float sm[64][65];
    const int tid = threadIdx.x;
    const int s0 = blockIdx.x * 64, h = blockIdx.y, b = blockIdx.z;
#pragma unroll
    for (int i = 0; i < 16; i++) {
        int lin = tid + i * 256;
        int rr = lin >> 6, d = lin & 63;
        sm[rr][d] = g_V[(size_t)(b * SEQ + s0 + rr) * DM + h * 64 + d];
    }
    __syncthreads();
#pragma unroll
    for (int i = 0; i < 16; i++) {
        int lin = tid + i * 256;
        int dd = lin >> 6, ss = lin & 63;
        size_t o = ((size_t)((b * NH + h) * 64 + dd)) * SEQ + s0 + ss;
        g_vt[o] = __float2half_rn(sm[ss][dd]);
    }
}

// ---------------------------------------------------------------------------
// zdenom: Z = 1/sum_h e_h; stores e_h (fp16) to g_E[b][h][q][k]
// Q fp16, K fp16 single: ONE MMA per fragment pair.
// ---------------------------------------------------------------------------
namespace {
constexpr int Z_QT    = 18432;                 // Q tile 128 x 144B
constexpr int Z_KT    = 9216;                  // K tile 64 x 144B
constexpr int Z_STAGE = Z_QT + Z_KT;           // 27648
constexpr int Z_SMEM  = 2 * Z_STAGE;           // 55296
}

__global__ __launch_bounds__(256)
void zdenom_mma()
{
    extern __shared__ __align__(16) char smem[];
    const uint32_t sb = smem_u32(smem);
    const int tid = threadIdx.x, lane = tid & 31, wid = tid >> 5;
    const int r = lane >> 2, c = lane & 3;
    const int b = blockIdx.z, q0 = blockIdx.y * 128, k0 = blockIdx.x * 64;

    auto issue = [&](int h, int s) {
        const uint32_t base = sb + s * Z_STAGE;
#pragma unroll
        for (int i = 0; i < 4; i++) {          // Q: 128 rows x 8 chunks
            int idx = tid + i * 256;
            int rr = idx >> 3, cc = idx & 7;
            cp16(base + rr * 144 + cc * 16,
                 g_q + (size_t)(b * SEQ + q0 + rr) * DM + h * 64 + cc * 8);
        }
#pragma unroll
        for (int i = 0; i < 2; i++) {          // K: 64 rows x 8 chunks
            int idx = tid + i * 256;
            int rr = idx >> 3, cc = idx & 7;
            cp16(base + Z_QT + rr * 144 + cc * 16,
                 g_k + (size_t)(b * SEQ + k0 + rr) * DM + h * 64 + cc * 8);
        }
        cp_commit();
    };

    issue(0, 0);
    issue(1, 1);

    float z[8][4];
#pragma unroll
    for (int i = 0; i < 8; i++)
#pragma unroll
        for (int j = 0; j < 4; j++) z[i][j] = 0.f;

    for (int h = 0; h < NH; h++) {
        if (h == NH - 1) cp_wait<0>(); else cp_wait<1>();
        __syncthreads();
        const char* st = smem + (h & 1) * Z_STAGE;
        const uint32_t* Q32 = (const uint32_t*)(st);
        const uint32_t* K32 = (const uint32_t*)(st + Z_QT);

        float sc[8][4];
#pragma unroll
        for (int i = 0; i < 8; i++)
#pragma unroll
            for (int j = 0; j < 4; j++) sc[i][j] = 0.f;

#pragma unroll
        for (int kk = 0; kk < 4; kk++) {
            uint32_t aq[4];
            {
                int row = wid * 16 + r;
                int w0 = row * 36 + kk * 8 + c;
                aq[0] = Q32[w0];     aq[1] = Q32[w0 + 288];
                aq[2] = Q32[w0 + 4]; aq[3] = Q32[w0 + 292];
            }
#pragma unroll
            for (int nt = 0; nt < 8; nt++) {
                uint32_t bk[2];
                int rn = nt * 8 + r;
                int w0 = rn * 36 + kk * 8 + c;
                bk[0] = K32[w0]; bk[1] = K32[w0 + 4];
                mma16816(sc[nt], aq, bk);
            }
        }

#pragma unroll
        for (int i = 0; i < 8; i++)
#pragma unroll
            for (int j = 0; j < 4; j++) {
                sc[i][j] = ex2(sc[i][j] * SCLOG2E);
                z[i][j] += sc[i][j];
            }
        {
            size_t eb = ((size_t)((b * NH + h) * SEQ) + q0 + wid * 16 + r) * SEQ + k0;
#pragma unroll
            for (int nt = 0; nt < 8; nt++) {
                *(uint32_t*)&g_E[eb + nt * 8 + 2 * c] = packh2(sc[nt][0], sc[nt][1]);
                *(uint32_t*)&g_E[eb + (size_t)8 * SEQ + nt * 8 + 2 * c] =
                    packh2(sc[nt][2], sc[nt][3]);
            }
        }

        __syncthreads();
        if (h + 2 < NH) issue(h + 2, h & 1);
    }

#pragma unroll
    for (int nt = 0; nt < 8; nt++) {
        int q = q0 + wid * 16 + r;
        int col = k0 + nt * 8 + 2 * c;
        *(float2*)&g_Z[(size_t)(b * SEQ + q) * SEQ + col] =
            make_float2(frcp(z[nt][0]), frcp(z[nt][1]));
        *(float2*)&g_Z[(size_t)(b * SEQ + q + 8) * SEQ + col] =
            make_float2(frcp(z[nt][2]), frcp(z[nt][3]));
    }
}

// ---------------------------------------------------------------------------
// attn (PV only): p = E .* rz (half2 mul); acc += p @ V (single fp16 V)
// ---------------------------------------------------------------------------
namespace {
constexpr int AE_T    = 18432;                 // E tile 128 x 144B
constexpr int AV_T    = 9216;                  // V tile 64 x 144B
constexpr int A_STAGE = AE_T + AV_T;           // 27648
constexpr int A_SMEM  = 2 * A_STAGE;           // 55296
}

__global__ __launch_bounds__(256)
void attn_mma()
{
    extern __shared__ __align__(16) char smem[];
    const uint32_t sb = smem_u32(smem);
    const int tid = threadIdx.x, lane = tid & 31, wid = tid >> 5;
    const int r = lane >> 2, c = lane & 3;
    const int b = blockIdx.z, h = blockIdx.y, q0 = blockIdx.x * 128;
    const int hc = h * 64;
    const __half* Eb = g_E + (size_t)(b * NH + h) * SEQ * SEQ;

    auto issue = [&](int kt, int s) {
        const uint32_t base = sb + s * A_STAGE;
#pragma unroll
        for (int i = 0; i < 4; i++) {        // E: 128 rows x 8 chunks
            int idx = tid + i * 256;
            int rr = idx >> 3, cc = idx & 7;
            cp16(base + rr * 144 + cc * 16,
                 Eb + (size_t)(q0 + rr) * SEQ + kt * 64 + cc * 8);
        }
#pragma unroll
        for (int i = 0; i < 2; i++) {        // V: 64 rows x 8 chunks
            int idx = tid + i * 256;
            int r2 = idx >> 3, cc = idx & 7;
            cp16(base + AE_T + r2 * 144 + cc * 16,
                 g_vt + (size_t)((b * NH + h) * 64 + r2) * SEQ + kt * 64 + cc * 8);
        }
        cp_commit();
    };

    issue(0, 0);
    issue(1, 1);

    float acc[8][4];
#pragma unroll
    for (int i = 0; i < 8; i++)
#pragma unroll
        for (int j = 0; j < 4; j++) acc[i][j] = 0.f;

    const int KT = SEQ / 64;   // 32
    for (int kt = 0; kt < KT; kt++) {
        // rz for this tile, packed to half2: [kk][pos]; pos 0=(row,k),1=(row,k+8),
        // 2=(row+8,k),3=(row+8,k+8)
        uint32_t rzh[4][4];
        {
            const float* Z0 = g_Z + (size_t)(b * SEQ + q0 + wid * 16 + r) * SEQ
                              + kt * 64 + 2 * c;
            const float* Z1 = Z0 + (size_t)8 * SEQ;
#pragma unroll
            for (int kk = 0; kk < 4; kk++) {
                float2 a0 = *(const float2*)(Z0 + kk * 16);
                float2 a1 = *(const float2*)(Z0 + kk * 16 + 8);
                float2 a2 = *(const float2*)(Z1 + kk * 16);
                float2 a3 = *(const float2*)(Z1 + kk * 16 + 8);
                rzh[kk][0] = packh2(a0.x, a0.y);
                rzh[kk][1] = packh2(a1.x, a1.y);
                rzh[kk][2] = packh2(a2.x, a2.y);
                rzh[kk][3] = packh2(a3.x, a3.y);
            }
        }
        if (kt == KT - 1) cp_wait<0>(); else cp_wait<1>();
        __syncthreads();
        const char* st = smem + (kt & 1) * A_STAGE;
        const uint32_t* E32 = (const uint32_t*)(st);
        const uint32_t* V32 = (const uint32_t*)(st + AE_T);

#pragma unroll
        for (int kk = 0; kk < 4; kk++) {
            uint32_t ap[4];
            {
                int w0 = (wid * 16 + r) * 36 + kk * 8 + c;
                ap[0] = hmul2u(E32[w0],       rzh[kk][0]);   // (row,   k)
                ap[1] = hmul2u(E32[w0 + 288], rzh[kk][2]);   // (row+8, k)
                ap[2] = hmul2u(E32[w0 + 4],   rzh[kk][1]);   // (row,   k+8)
                ap[3] = hmul2u(E32[w0 + 292], rzh[kk][3]);   // (row+8, k+8)
            }
#pragma unroll
            for (int dt = 0; dt < 8; dt++) {
                uint32_t bv[2];
                int w1 = (dt * 8 + r) * 36 + kk * 8 + c;
                bv[0] = V32[w1]; bv[1] = V32[w1 + 4];
                mma16816(acc[dt], ap, bv);
            }
        }
        __syncthreads();
        if (kt + 2 < KT) issue(kt + 2, kt & 1);
    }

    // epilogue: context -> fp16 single
#pragma unroll
    for (int dt = 0; dt < 8; dt++) {
        int row = b * SEQ + q0 + wid * 16 + r;
        int col = hc + dt * 8 + 2 * c;
        *(uint32_t*)&g_c[(size_t)row * DM + col]       = packh2(acc[dt][0], acc[dt][1]);
        *(uint32_t*)&g_c[(size_t)(row + 8) * DM + col] = packh2(acc[dt][2], acc[dt][3]);
    }
}

// ---------------------------------------------------------------------------
extern "C" void kernel_launch(void* const* d_in, const int* in_sizes, int n_in,
                              void* d_out, int out_size)
{
    (void)in_sizes; (void)n_in; (void)out_size;
    const float* x  = (const float*)d_in[0];
    const float* Wq = (const float*)d_in[1];
    const float* bq = (const float*)d_in[2];
    const float* Wk = (const float*)d_in[3];
    const float* bk = (const float*)d_in[4];
    const float* Wv = (const float*)d_in[5];
    const float* bv = (const float*)d_in[6];
    const float* Wo = (const float*)d_in[7];
    const float* bo = (const float*)d_in[8];
    float* out = (float*)d_out;

    __half *xp, *wh, *wl, *qp, *kp, *cp;
    float* Vp;
    cudaGetSymbolAddress((void**)&xp, g_x);
    cudaGetSymbolAddress((void**)&wh, g_wh);
    cudaGetSymbolAddress((void**)&wl, g_wl);
    cudaGetSymbolAddress((void**)&qp, g_q);
    cudaGetSymbolAddress((void**)&kp, g_k);
    cudaGetSymbolAddress((void**)&cp, g_c);
    cudaGetSymbolAddress((void**)&Vp, g_V);

    cudaFuncSetAttribute(gemm_mma<0>, cudaFuncAttributeMaxDynamicSharedMemorySize, G_SMEM);
    cudaFuncSetAttribute(gemm_mma<1>, cudaFuncAttributeMaxDynamicSharedMemorySize, G_SMEM);
    cudaFuncSetAttribute(zdenom_mma,  cudaFuncAttributeMaxDynamicSharedMemorySize, Z_SMEM);
    cudaFuncSetAttribute(attn_mma,    cudaFuncAttributeMaxDynamicSharedMemorySize, A_SMEM);

    const int NX = NTOK * DM;   // 4M
    const int NW = DM * DM;     // 1M
    cvt_h<<<NX / 1024, 256>>>(x, xp, NX);
    cvt_w4<<<dim3(NW / 1024, 4), 256>>>(Wq, Wk, Wv, Wo, wh, wl);

    dim3 gproj(DM / 128, NTOK / 128);   // (8, 32)
    gemm_mma<1><<<gproj, 256, G_SMEM>>>(xp, wh + 0 * NW, wl + 0 * NW, bq,
                                        nullptr, qp, NTOK, DM, DM);
    gemm_mma<1><<<gproj, 256, G_SMEM>>>(xp, wh + 1 * NW, wl + 1 * NW, bk,
                                        nullptr, kp, NTOK, DM, DM);
    gemm_mma<0><<<gproj, 256, G_SMEM>>>(xp, wh + 2 * NW, wl + 2 * NW, bv,
                                        Vp, nullptr, NTOK, DM, DM);

    zdenom_mma<<<dim3(SEQ / 64, SEQ / 128, BT), 256, Z_SMEM>>>();

    vtrans<<<dim3(SEQ / 64, NH, BT), 256>>>();

    attn_mma<<<dim3(SEQ / 128, NH, BT), 256, A_SMEM>>>();

    gemm_mma<0><<<gproj, 256, G_SMEM>>>(cp, wh + 3 * NW, wl + 3 * NW, bo,
                                        out, nullptr, NTOK, DM, DM);
}

// round 12
// speedup vs baseline: 1.7665x; 1.1874x over previous
#include <cuda_runtime.h>
#include <cuda_bf16.h>
#include <cuda_fp16.h>
#include <cstdint>

namespace {
constexpr int SEQ = 2048;
constexpr int BT  = 2;
constexpr int DM  = 1024;
constexpr int NH  = 16;
constexpr int NTOK = BT * SEQ;     // 4096
constexpr float SCLOG2E = 0.125f * 1.4426950408889634f;  // scale * log2(e)
}

// ---------------- device scratch (allocation-free) ----------------
__device__ __half g_q [NTOK * DM];                   // Q, fp16
__device__ __half g_k [NTOK * DM];                   // K, fp16
__device__ __half g_v [NTOK * DM];                   // V, fp16 [tok][DM]
__device__ __half g_vt[NTOK * DM];                   // [b][h][d][s], fp16
__device__ __half g_c [NTOK * DM];                   // context, fp16
__device__ float  g_Z [BT * SEQ * SEQ];              // reciprocal denom
__device__ __half g_E [(size_t)BT * NH * SEQ * SEQ]; // exp(scores), [b][h][q][k]
__device__ __half g_x [NTOK * DM];                   // x, fp16
__device__ __half g_w [4][DM * DM];                  // weights, fp16

// ---------------- tiny PTX helpers (sm_103-safe) ----------------
__device__ __forceinline__ uint32_t smem_u32(const void* p) {
    uint32_t a;
    asm("{ .reg .u64 t; cvta.to.shared.u64 t, %1; cvt.u32.u64 %0, t; }" : "=r"(a) : "l"(p));
    return a;
}
__device__ __forceinline__ void cp16(uint32_t dst, const void* src) {
    asm volatile("cp.async.cg.shared.global [%0], [%1], 16;" :: "r"(dst), "l"(src) : "memory");
}
__device__ __forceinline__ void cp_commit() {
    asm volatile("cp.async.commit_group;" ::: "memory");
}
template <int N> __device__ __forceinline__ void cp_wait() {
    asm volatile("cp.async.wait_group %0;" :: "n"(N) : "memory");
}
__device__ __forceinline__ void mma16816(float* d, const uint32_t* a, const uint32_t* b) {
    asm volatile(
        "mma.sync.aligned.m16n8k16.row.col.f32.f16.f16.f32 "
        "{%0,%1,%2,%3}, {%4,%5,%6,%7}, {%8,%9}, {%0,%1,%2,%3};"
        : "+f"(d[0]), "+f"(d[1]), "+f"(d[2]), "+f"(d[3])
        : "r"(a[0]), "r"(a[1]), "r"(a[2]), "r"(a[3]), "r"(b[0]), "r"(b[1]));
}
__device__ __forceinline__ float ex2(float x) {
    float y; asm("ex2.approx.ftz.f32 %0, %1;" : "=f"(y) : "f"(x)); return y;
}
__device__ __forceinline__ float frcp(float x) {
    float y; asm("rcp.approx.ftz.f32 %0, %1;" : "=f"(y) : "f"(x)); return y;
}
// pack two fp32 -> f16x2 reg: low half = `lo` (lower column index)
__device__ __forceinline__ uint32_t packh2(float lo, float hi) {
    uint32_t r; asm("cvt.rn.f16x2.f32 %0, %1, %2;" : "=r"(r) : "f"(hi), "f"(lo)); return r;
}
__device__ __forceinline__ uint32_t hmul2u(uint32_t a, uint32_t b) {
    __half2 r = __hmul2(*(const __half2*)&a, *(const __half2*)&b);
    return *(uint32_t*)&r;
}

// ---------------------------------------------------------------------------
// fp32 -> fp16 (for x)
// ---------------------------------------------------------------------------
__global__ __launch_bounds__(256)
void cvt_h(const float* __restrict__ in, __half* __restrict__ out, int n)
{
    int i = (blockIdx.x * 256 + threadIdx.x) * 4;
    if (i >= n) return;
    float4 v = *(const float4*)(in + i);
    ushort4 o;
    o.x = __half_as_ushort(__float2half_rn(v.x));
    o.y = __half_as_ushort(__float2half_rn(v.y));
    o.z = __half_as_ushort(__float2half_rn(v.z));
    o.w = __half_as_ushort(__float2half_rn(v.w));
    *(ushort4*)((unsigned short*)out + i) = o;
}

// all 4 weights: fp32 -> fp16
__global__ __launch_bounds__(256)
void cvt_w4(const float* __restrict__ W0, const float* __restrict__ W1,
            const float* __restrict__ W2, const float* __restrict__ W3,
            __half* __restrict__ out)
{
    const int NW = DM * DM;
    const float* in = (blockIdx.y == 0) ? W0 : (blockIdx.y == 1) ? W1
                    : (blockIdx.y == 2) ? W2 : W3;
    int i = (blockIdx.x * 256 + threadIdx.x) * 4;
    size_t o = (size_t)blockIdx.y * NW + i;
    float4 v = *(const float4*)(in + i);
    ushort4 u;
    u.x = __half_as_ushort(__float2half_rn(v.x));
    u.y = __half_as_ushort(__float2half_rn(v.y));
    u.z = __half_as_ushort(__float2half_rn(v.z));
    u.w = __half_as_ushort(__float2half_rn(v.w));
    *(ushort4*)((unsigned short*)out + o) = u;
}

// ---------------------------------------------------------------------------
// HMMA fp16 GEMM: C = A * B^T + bias (A, B fp16 single)
// CTA 128x128, BK=64, 8 warps, 3-stage cp.async pipeline.
// OUT: 0 = fp32 Cf, 1 = fp16 Ch
// ---------------------------------------------------------------------------
namespace {
constexpr int G_RSB   = 144;
constexpr int G_TILE  = 128 * G_RSB;       // 18432
constexpr int G_STAGE = 2 * G_TILE;        // 36864 (A, B)
constexpr int G_SMEM  = 3 * G_STAGE;       // 110592
}

template <int OUT>
__global__ __launch_bounds__(256, 2)
void gemm_mma(const __half* __restrict__ A, const __half* __restrict__ B,
              const float* __restrict__ bias,
              float* __restrict__ Cf, __half* __restrict__ Ch,
              int M, int N, int K)
{
    extern __shared__ __align__(16) char smem[];
    const uint32_t sb = smem_u32(smem);
    const int tid = threadIdx.x, lane = tid & 31, wid = tid >> 5;
    const int wm = wid >> 2, wn = wid & 3;
    const int r = lane >> 2, c = lane & 3;
    const int m0 = blockIdx.y * 128, n0 = blockIdx.x * 128;
    const int KT = K / 64;

    float acc[4][4][4];
#pragma unroll
    for (int i = 0; i < 4; i++)
#pragma unroll
        for (int j = 0; j < 4; j++)
#pragma unroll
            for (int q = 0; q < 4; q++) acc[i][j][q] = 0.f;

    auto issue = [&](int kt, int s) {
        const int k0 = kt * 64;
#pragma unroll
        for (int a = 0; a < 2; a++) {
            const __half* g = (a == 0) ? A : B;
            const int rbase = (a == 0) ? m0 : n0;
            const uint32_t dstb = sb + s * G_STAGE + a * G_TILE;
#pragma unroll
            for (int i = 0; i < 4; i++) {
                int idx = tid + i * 256;
                int rr = idx >> 3, cc = idx & 7;
                cp16(dstb + rr * G_RSB + cc * 16,
                     g + (size_t)(rbase + rr) * K + k0 + cc * 8);
            }
        }
        cp_commit();
    };

    issue(0, 0);
    issue(1, 1);
    issue(2, 2);

    for (int kt = 0; kt < KT; kt++) {
        if (kt < KT - 2) cp_wait<2>();
        else if (kt == KT - 2) cp_wait<1>();
        else cp_wait<0>();
        __syncthreads();
        const char* st = smem + (kt % 3) * G_STAGE;
        const uint32_t* A32 = (const uint32_t*)(st);
        const uint32_t* B32 = (const uint32_t*)(st + G_TILE);

#pragma unroll
        for (int kk = 0; kk < 4; kk++) {
            uint32_t ah[4][4], bh[4][2];
#pragma unroll
            for (int mt = 0; mt < 4; mt++) {
                int row = wm * 64 + mt * 16 + r;
                int w0 = row * 36 + kk * 8 + c;
                ah[mt][0] = A32[w0];     ah[mt][1] = A32[w0 + 288];
                ah[mt][2] = A32[w0 + 4]; ah[mt][3] = A32[w0 + 292];
            }
#pragma unroll
            for (int nt = 0; nt < 4; nt++) {
                int rn = wn * 32 + nt * 8 + r;
                int w0 = rn * 36 + kk * 8 + c;
                bh[nt][0] = B32[w0]; bh[nt][1] = B32[w0 + 4];
            }
#pragma unroll
            for (int mt = 0; mt < 4; mt++)
#pragma unroll
                for (int nt = 0; nt < 4; nt++)
                    mma16816(acc[mt][nt], ah[mt], bh[nt]);
        }
        __syncthreads();
        if (kt + 3 < KT) issue(kt + 3, kt % 3);
    }

#pragma unroll
    for (int mt = 0; mt < 4; mt++) {
#pragma unroll
        for (int nt = 0; nt < 4; nt++) {
            int row = m0 + wm * 64 + mt * 16 + r;
            int col = n0 + wn * 32 + nt * 8 + 2 * c;
            float b0 = bias[col], b1 = bias[col + 1];
            float f0 = acc[mt][nt][0] + b0, f1 = acc[mt][nt][1] + b1;
            float f2 = acc[mt][nt][2] + b0, f3 = acc[mt][nt][3] + b1;
            if (OUT == 0) {
                *(float2*)&Cf[(size_t)row * N + col]       = make_float2(f0, f1);
                *(float2*)&Cf[(size_t)(row + 8) * N + col] = make_float2(f2, f3);
            } else {
                *(uint32_t*)&Ch[(size_t)row * N + col]       = packh2(f0, f1);
                *(uint32_t*)&Ch[(size_t)(row + 8) * N + col] = packh2(f2, f3);
            }
        }
    }
}

// ---------------------------------------------------------------------------
// V transpose: g_v fp16 [tok][DM] -> fp16 [b][h][d][s]
// ---------------------------------------------------------------------------
__global__ __launch_bounds__(256)
void vtrans()
{
    __shared__ __half sm[64][70];   // 70: conflict-free column reads
    const int tid = threadIdx.x;
    const int s0 = blockIdx.x * 64, h = blockIdx.y, b = blockIdx.z;
#pragma unroll
    for (int i = 0; i < 16; i++) {
        int lin = tid + i * 256;
        int rr = lin >> 6, d = lin & 63;
        sm[rr][d] = g_v[(size_t)(b * SEQ + s0 + rr) * DM + h * 64 + d];
    }
    __syncthreads();
#pragma unroll
    for (int i = 0; i < 16; i++) {
        int lin = tid + i * 256;
        int dd = lin >> 6, ss = lin & 63;
        size_t o = ((size_t)((b * NH + h) * 64 + dd)) * SEQ + s0 + ss;
        g_vt[o] = sm[ss][dd];
    }
}

// ---------------------------------------------------------------------------
// zdenom: Z = 1/sum_h e_h; stores e_h (fp16) to g_E[b][h][q][k]
// ---------------------------------------------------------------------------
namespace {
constexpr int Z_QT    = 18432;                 // Q tile 128 x 144B
constexpr int Z_KT    = 9216;                  // K tile 64 x 144B
constexpr int Z_STAGE = Z_QT + Z_KT;           // 27648
constexpr int Z_SMEM  = 2 * Z_STAGE;           // 55296
}

__global__ __launch_bounds__(256)
void zdenom_mma()
{
    extern __shared__ __align__(16) char smem[];
    const uint32_t sb = smem_u32(smem);
    const int tid = threadIdx.x, lane = tid & 31, wid = tid >> 5;
    const int r = lane >> 2, c = lane & 3;
    const int b = blockIdx.z, q0 = blockIdx.y * 128, k0 = blockIdx.x * 64;

    auto issue = [&](int h, int s) {
        const uint32_t base = sb + s * Z_STAGE;
#pragma unroll
        for (int i = 0; i < 4; i++) {          // Q: 128 rows x 8 chunks
            int idx = tid + i * 256;
            int rr = idx >> 3, cc = idx & 7;
            cp16(base + rr * 144 + cc * 16,
                 g_q + (size_t)(b * SEQ + q0 + rr) * DM + h * 64 + cc * 8);
        }
#pragma unroll
        for (int i = 0; i < 2; i++) {          // K: 64 rows x 8 chunks
            int idx = tid + i * 256;
            int rr = idx >> 3, cc = idx & 7;
            cp16(base + Z_QT + rr * 144 + cc * 16,
                 g_k + (size_t)(b * SEQ + k0 + rr) * DM + h * 64 + cc * 8);
        }
        cp_commit();
    };

    issue(0, 0);
    issue(1, 1);

    float z[8][4];
#pragma unroll
    for (int i = 0; i < 8; i++)
#pragma unroll
        for (int j = 0; j < 4; j++) z[i][j] = 0.f;

    for (int h = 0; h < NH; h++) {
        if (h == NH - 1) cp_wait<0>(); else cp_wait<1>();
        __syncthreads();
        const char* st = smem + (h & 1) * Z_STAGE;
        const uint32_t* Q32 = (const uint32_t*)(st);
        const uint32_t* K32 = (const uint32_t*)(st + Z_QT);

        float sc[8][4];
#pragma unroll
        for (int i = 0; i < 8; i++)
#pragma unroll
            for (int j = 0; j < 4; j++) sc[i][j] = 0.f;

#pragma unroll
        for (int kk = 0; kk < 4; kk++) {
            uint32_t aq[4];
            {
                int row = wid * 16 + r;
                int w0 = row * 36 + kk * 8 + c;
                aq[0] = Q32[w0];     aq[1] = Q32[w0 + 288];
                aq[2] = Q32[w0 + 4]; aq[3] = Q32[w0 + 292];
            }
#pragma unroll
            for (int nt = 0; nt < 8; nt++) {
                uint32_t bk[2];
                int rn = nt * 8 + r;
                int w0 = rn * 36 + kk * 8 + c;
                bk[0] = K32[w0]; bk[1] = K32[w0 + 4];
                mma16816(sc[nt], aq, bk);
            }
        }

#pragma unroll
        for (int i = 0; i < 8; i++)
#pragma unroll
            for (int j = 0; j < 4; j++) {
                sc[i][j] = ex2(sc[i][j] * SCLOG2E);
                z[i][j] += sc[i][j];
            }
        {
            size_t eb = ((size_t)((b * NH + h) * SEQ) + q0 + wid * 16 + r) * SEQ + k0;
#pragma unroll
            for (int nt = 0; nt < 8; nt++) {
                *(uint32_t*)&g_E[eb + nt * 8 + 2 * c] = packh2(sc[nt][0], sc[nt][1]);
                *(uint32_t*)&g_E[eb + (size_t)8 * SEQ + nt * 8 + 2 * c] =
                    packh2(sc[nt][2], sc[nt][3]);
            }
        }

        __syncthreads();
        if (h + 2 < NH) issue(h + 2, h & 1);
    }

#pragma unroll
    for (int nt = 0; nt < 8; nt++) {
        int q = q0 + wid * 16 + r;
        int col = k0 + nt * 8 + 2 * c;
        *(float2*)&g_Z[(size_t)(b * SEQ + q) * SEQ + col] =
            make_float2(frcp(z[nt][0]), frcp(z[nt][1]));
        *(float2*)&g_Z[(size_t)(b * SEQ + q + 8) * SEQ + col] =
            make_float2(frcp(z[nt][2]), frcp(z[nt][3]));
    }
}

// ---------------------------------------------------------------------------
// attn (PV only): p = E .* rz (half2 mul); acc += p @ V
// ---------------------------------------------------------------------------
namespace {
constexpr int AE_T    = 18432;                 // E tile 128 x 144B
constexpr int AV_T    = 9216;                  // V tile 64 x 144B
constexpr int A_STAGE = AE_T + AV_T;           // 27648
constexpr int A_SMEM  = 2 * A_STAGE;           // 55296
}

__global__ __launch_bounds__(256)
void attn_mma()
{
    extern __shared__ __align__(16) char smem[];
    const uint32_t sb = smem_u32(smem);
    const int tid = threadIdx.x, lane = tid & 31, wid = tid >> 5;
    const int r = lane >> 2, c = lane & 3;
    const int b = blockIdx.z, h = blockIdx.y, q0 = blockIdx.x * 128;
    const int hc = h * 64;
    const __half* Eb = g_E + (size_t)(b * NH + h) * SEQ * SEQ;

    auto issue = [&](int kt, int s) {
        const uint32_t base = sb + s * A_STAGE;
#pragma unroll
        for (int i = 0; i < 4; i++) {        // E: 128 rows x 8 chunks
            int idx = tid + i * 256;
            int rr = idx >> 3, cc = idx & 7;
            cp16(base + rr * 144 + cc * 16,
                 Eb + (size_t)(q0 + rr) * SEQ + kt * 64 + cc * 8);
        }
#pragma unroll
        for (int i = 0; i < 2; i++) {        // V: 64 rows x 8 chunks
            int idx = tid + i * 256;
            int r2 = idx >> 3, cc = idx & 7;
            cp16(base + AE_T + r2 * 144 + cc * 16,
                 g_vt + (size_t)((b * NH + h) * 64 + r2) * SEQ + kt * 64 + cc * 8);
        }
        cp_commit();
    };

    issue(0, 0);
    issue(1, 1);

    float acc[8][4];
#pragma unroll
    for (int i = 0; i < 8; i++)
#pragma unroll
        for (int j = 0; j < 4; j++) acc[i][j] = 0.f;

    const int KT = SEQ / 64;   // 32
    for (int kt = 0; kt < KT; kt++) {
        uint32_t rzh[4][4];
        {
            const float* Z0 = g_Z + (size_t)(b * SEQ + q0 + wid * 16 + r) * SEQ
                              + kt * 64 + 2 * c;
            const float* Z1 = Z0 + (size_t)8 * SEQ;
#pragma unroll
            for (int kk = 0; kk < 4; kk++) {
                float2 a0 = *(const float2*)(Z0 + kk * 16);
                float2 a1 = *(const float2*)(Z0 + kk * 16 + 8);
                float2 a2 = *(const float2*)(Z1 + kk * 16);
                float2 a3 = *(const float2*)(Z1 + kk * 16 + 8);
                rzh[kk][0] = packh2(a0.x, a0.y);
                rzh[kk][1] = packh2(a1.x, a1.y);
                rzh[kk][2] = packh2(a2.x, a2.y);
                rzh[kk][3] = packh2(a3.x, a3.y);
            }
        }
        if (kt == KT - 1) cp_wait<0>(); else cp_wait<1>();
        __syncthreads();
        const char* st = smem + (kt & 1) * A_STAGE;
        const uint32_t* E32 = (const uint32_t*)(st);
        const uint32_t* V32 = (const uint32_t*)(st + AE_T);

#pragma unroll
        for (int kk = 0; kk < 4; kk++) {
            uint32_t ap[4];
            {
                int w0 = (wid * 16 + r) * 36 + kk * 8 + c;
                ap[0] = hmul2u(E32[w0],       rzh[kk][0]);   // (row,   k)
                ap[1] = hmul2u(E32[w0 + 288], rzh[kk][2]);   // (row+8, k)
                ap[2] = hmul2u(E32[w0 + 4],   rzh[kk][1]);   // (row,   k+8)
                ap[3] = hmul2u(E32[w0 + 292], rzh[kk][3]);   // (row+8, k+8)
            }
#pragma unroll
            for (int dt = 0; dt < 8; dt++) {
                uint32_t bv[2];
                int w1 = (dt * 8 + r) * 36 + kk * 8 + c;
                bv[0] = V32[w1]; bv[1] = V32[w1 + 4];
                mma16816(acc[dt], ap, bv);
            }
        }
        __syncthreads();
        if (kt + 2 < KT) issue(kt + 2, kt & 1);
    }

    // epilogue: context -> fp16
#pragma unroll
    for (int dt = 0; dt < 8; dt++) {
        int row = b * SEQ + q0 + wid * 16 + r;
        int col = hc + dt * 8 + 2 * c;
        *(uint32_t*)&g_c[(size_t)row * DM + col]       = packh2(acc[dt][0], acc[dt][1]);
        *(uint32_t*)&g_c[(size_t)(row + 8) * DM + col] = packh2(acc[dt][2], acc[dt][3]);
    }
}

// ---------------------------------------------------------------------------
extern "C" void kernel_launch(void* const* d_in, const int* in_sizes, int n_in,
                              void* d_out, int out_size)
{
    (void)in_sizes; (void)n_in; (void)out_size;
    const float* x  = (const float*)d_in[0];
    const float* Wq = (const float*)d_in[1];
    const float* bq = (const float*)d_in[2];
    const float* Wk = (const float*)d_in[3];
    const float* bk = (const float*)d_in[4];
    const float* Wv = (const float*)d_in[5];
    const float* bv = (const float*)d_in[6];
    const float* Wo = (const float*)d_in[7];
    const float* bo = (const float*)d_in[8];
    float* out = (float*)d_out;

    __half *xp, *wp, *qp, *kp, *vp, *cp;
    cudaGetSymbolAddress((void**)&xp, g_x);
    cudaGetSymbolAddress((void**)&wp, g_w);
    cudaGetSymbolAddress((void**)&qp, g_q);
    cudaGetSymbolAddress((void**)&kp, g_k);
    cudaGetSymbolAddress((void**)&vp, g_v);
    cudaGetSymbolAddress((void**)&cp, g_c);

    cudaFuncSetAttribute(gemm_mma<0>, cudaFuncAttributeMaxDynamicSharedMemorySize, G_SMEM);
    cudaFuncSetAttribute(gemm_mma<1>, cudaFuncAttributeMaxDynamicSharedMemorySize, G_SMEM);
    cudaFuncSetAttribute(zdenom_mma,  cudaFuncAttributeMaxDynamicSharedMemorySize, Z_SMEM);
    cudaFuncSetAttribute(attn_mma,    cudaFuncAttributeMaxDynamicSharedMemorySize, A_SMEM);

    const int NX = NTOK * DM;   // 4M
    const int NW = DM * DM;     // 1M
    cvt_h<<<NX / 1024, 256>>>(x, xp, NX);
    cvt_w4<<<dim3(NW / 1024, 4), 256>>>(Wq, Wk, Wv, Wo, wp);

    dim3 gproj(DM / 128, NTOK / 128);   // (8, 32)
    gemm_mma<1><<<gproj, 256, G_SMEM>>>(xp, wp + 0 * NW, bq, nullptr, qp, NTOK, DM, DM);
    gemm_mma<1><<<gproj, 256, G_SMEM>>>(xp, wp + 1 * NW, bk, nullptr, kp, NTOK, DM, DM);
    gemm_mma<1><<<gproj, 256, G_SMEM>>>(xp, wp + 2 * NW, bv, nullptr, vp, NTOK, DM, DM);

    zdenom_mma<<<dim3(SEQ / 64, SEQ / 128, BT), 256, Z_SMEM>>>();

    vtrans<<<dim3(SEQ / 64, NH, BT), 256>>>();

    attn_mma<<<dim3(SEQ / 128, NH, BT), 256, A_SMEM>>>();

    gemm_mma<0><<<gproj, 256, G_SMEM>>>(cp, wp + 3 * NW, bo, out, nullptr, NTOK, DM, DM);
}

// round 13
// speedup vs baseline: 1.8870x; 1.0682x over previous
#include <cuda_runtime.h>
#include <cuda_bf16.h>
#include <cuda_fp16.h>
#include <cstdint>

namespace {
constexpr int SEQ = 2048;
constexpr int BT  = 2;
constexpr int DM  = 1024;
constexpr int NH  = 16;
constexpr int NTOK = BT * SEQ;     // 4096
constexpr float SCLOG2E = 0.125f * 1.4426950408889634f;  // scale * log2(e)
}

// ---------------- device scratch (allocation-free) ----------------
__device__ __half g_q [NTOK * DM];                   // Q, fp16
__device__ __half g_k [NTOK * DM];                   // K, fp16
__device__ __half g_v [NTOK * DM];                   // V, fp16 [tok][DM]
__device__ __half g_vt[NTOK * DM];                   // [b][h][d][s], fp16
__device__ __half g_c [NTOK * DM];                   // context, fp16
__device__ float  g_Z [BT * SEQ * SEQ];              // reciprocal denom
__device__ __half g_E [(size_t)BT * NH * SEQ * SEQ]; // exp(scores), [b][h][q][k]
__device__ __half g_x [NTOK * DM];                   // x, fp16
__device__ __half g_w [4][DM * DM];                  // weights, fp16

// ---------------- tiny PTX helpers (sm_103-safe) ----------------
__device__ __forceinline__ uint32_t smem_u32(const void* p) {
    uint32_t a;
    asm("{ .reg .u64 t; cvta.to.shared.u64 t, %1; cvt.u32.u64 %0, t; }" : "=r"(a) : "l"(p));
    return a;
}
__device__ __forceinline__ void cp16(uint32_t dst, const void* src) {
    asm volatile("cp.async.cg.shared.global [%0], [%1], 16;" :: "r"(dst), "l"(src) : "memory");
}
__device__ __forceinline__ void cp_commit() {
    asm volatile("cp.async.commit_group;" ::: "memory");
}
template <int N> __device__ __forceinline__ void cp_wait() {
    asm volatile("cp.async.wait_group %0;" :: "n"(N) : "memory");
}
__device__ __forceinline__ void mma16816(float* d, const uint32_t* a, const uint32_t* b) {
    asm volatile(
        "mma.sync.aligned.m16n8k16.row.col.f32.f16.f16.f32 "
        "{%0,%1,%2,%3}, {%4,%5,%6,%7}, {%8,%9}, {%0,%1,%2,%3};"
        : "+f"(d[0]), "+f"(d[1]), "+f"(d[2]), "+f"(d[3])
        : "r"(a[0]), "r"(a[1]), "r"(a[2]), "r"(a[3]), "r"(b[0]), "r"(b[1]));
}
__device__ __forceinline__ float ex2(float x) {
    float y; asm("ex2.approx.ftz.f32 %0, %1;" : "=f"(y) : "f"(x)); return y;
}
__device__ __forceinline__ float frcp(float x) {
    float y; asm("rcp.approx.ftz.f32 %0, %1;" : "=f"(y) : "f"(x)); return y;
}
// pack two fp32 -> f16x2 reg: low half = `lo` (lower column index)
__device__ __forceinline__ uint32_t packh2(float lo, float hi) {
    uint32_t r; asm("cvt.rn.f16x2.f32 %0, %1, %2;" : "=r"(r) : "f"(hi), "f"(lo)); return r;
}
__device__ __forceinline__ uint32_t hmul2u(uint32_t a, uint32_t b) {
    __half2 r = __hmul2(*(const __half2*)&a, *(const __half2*)&b);
    return *(uint32_t*)&r;
}

// ---------------------------------------------------------------------------
// One launch: x (y=0) and all 4 weights (y=1) -> fp16
// ---------------------------------------------------------------------------
__global__ __launch_bounds__(256)
void cvt_all(const float* __restrict__ x,
             const float* __restrict__ W0, const float* __restrict__ W1,
             const float* __restrict__ W2, const float* __restrict__ W3,
             __half* __restrict__ xo, __half* __restrict__ wo)
{
    const int NW = DM * DM;
    int i = (blockIdx.x * 256 + threadIdx.x) * 4;   // 0 .. 4M
    const float* in;
    __half* out;
    if (blockIdx.y == 0) { in = x; out = xo; }
    else {
        int w = i >> 20;                             // NW = 1<<20
        in  = (w == 0) ? W0 : (w == 1) ? W1 : (w == 2) ? W2 : W3;
        in -= (size_t)w << 20;                       // rebase so in+i is correct
        out = wo;
    }
    float4 v = *(const float4*)(in + i);
    ushort4 o;
    o.x = __half_as_ushort(__float2half_rn(v.x));
    o.y = __half_as_ushort(__float2half_rn(v.y));
    o.z = __half_as_ushort(__float2half_rn(v.z));
    o.w = __half_as_ushort(__float2half_rn(v.w));
    *(ushort4*)((unsigned short*)out + i) = o;
}

// ---------------------------------------------------------------------------
// HMMA fp16 GEMM: C = A * B^T + bias. grid.z selects (B, bias, out) triple.
// CTA 128x128, BK=64, 8 warps, 3-stage cp.async, single sync per k-tile.
// OUT: 0 = fp32, 1 = fp16
// ---------------------------------------------------------------------------
namespace {
constexpr int G_RSB   = 144;
constexpr int G_TILE  = 128 * G_RSB;       // 18432
constexpr int G_STAGE = 2 * G_TILE;        // 36864 (A, B)
constexpr int G_SMEM  = 3 * G_STAGE;       // 110592
}

template <int OUT>
__global__ __launch_bounds__(256, 2)
void gemm_mma(const __half* __restrict__ A,
              const __half* __restrict__ B0, const __half* __restrict__ B1,
              const __half* __restrict__ B2,
              const float* __restrict__ bias0, const float* __restrict__ bias1,
              const float* __restrict__ bias2,
              float* __restrict__ Cf,
              __half* __restrict__ Ch0, __half* __restrict__ Ch1,
              __half* __restrict__ Ch2,
              int M, int N, int K)
{
    extern __shared__ __align__(16) char smem[];
    const uint32_t sb = smem_u32(smem);
    const int tid = threadIdx.x, lane = tid & 31, wid = tid >> 5;
    const int wm = wid >> 2, wn = wid & 3;
    const int r = lane >> 2, c = lane & 3;
    const int m0 = blockIdx.y * 128, n0 = blockIdx.x * 128;
    const int z = blockIdx.z;
    const __half* B = (z == 0) ? B0 : (z == 1) ? B1 : B2;
    const float* bias = (z == 0) ? bias0 : (z == 1) ? bias1 : bias2;
    __half* Ch = (z == 0) ? Ch0 : (z == 1) ? Ch1 : Ch2;
    const int KT = K / 64;

    float acc[4][4][4];
#pragma unroll
    for (int i = 0; i < 4; i++)
#pragma unroll
        for (int j = 0; j < 4; j++)
#pragma unroll
            for (int q = 0; q < 4; q++) acc[i][j][q] = 0.f;

    auto issue = [&](int kt, int s) {
        const int k0 = kt * 64;
#pragma unroll
        for (int a = 0; a < 2; a++) {
            const __half* g = (a == 0) ? A : B;
            const int rbase = (a == 0) ? m0 : n0;
            const uint32_t dstb = sb + s * G_STAGE + a * G_TILE;
#pragma unroll
            for (int i = 0; i < 4; i++) {
                int idx = tid + i * 256;
                int rr = idx >> 3, cc = idx & 7;
                cp16(dstb + rr * G_RSB + cc * 16,
                     g + (size_t)(rbase + rr) * K + k0 + cc * 8);
            }
        }
        cp_commit();
    };

    issue(0, 0);
    issue(1, 1);

    for (int kt = 0; kt < KT; kt++) {
        if (kt == KT - 1) cp_wait<0>(); else cp_wait<1>();
        __syncthreads();
        if (kt + 2 < KT) issue(kt + 2, (kt + 2) % 3);   // into stage (kt-1)%3, drained
        const char* st = smem + (kt % 3) * G_STAGE;
        const uint32_t* A32 = (const uint32_t*)(st);
        const uint32_t* B32 = (const uint32_t*)(st + G_TILE);

#pragma unroll
        for (int kk = 0; kk < 4; kk++) {
            uint32_t ah[4][4], bh[4][2];
#pragma unroll
            for (int mt = 0; mt < 4; mt++) {
                int row = wm * 64 + mt * 16 + r;
                int w0 = row * 36 + kk * 8 + c;
                ah[mt][0] = A32[w0];     ah[mt][1] = A32[w0 + 288];
                ah[mt][2] = A32[w0 + 4]; ah[mt][3] = A32[w0 + 292];
            }
#pragma unroll
            for (int nt = 0; nt < 4; nt++) {
                int rn = wn * 32 + nt * 8 + r;
                int w0 = rn * 36 + kk * 8 + c;
                bh[nt][0] = B32[w0]; bh[nt][1] = B32[w0 + 4];
            }
#pragma unroll
            for (int mt = 0; mt < 4; mt++)
#pragma unroll
                for (int nt = 0; nt < 4; nt++)
                    mma16816(acc[mt][nt], ah[mt], bh[nt]);
        }
    }

#pragma unroll
    for (int mt = 0; mt < 4; mt++) {
#pragma unroll
        for (int nt = 0; nt < 4; nt++) {
            int row = m0 + wm * 64 + mt * 16 + r;
            int col = n0 + wn * 32 + nt * 8 + 2 * c;
            float b0 = bias[col], b1 = bias[col + 1];
            float f0 = acc[mt][nt][0] + b0, f1 = acc[mt][nt][1] + b1;
            float f2 = acc[mt][nt][2] + b0, f3 = acc[mt][nt][3] + b1;
            if (OUT == 0) {
                *(float2*)&Cf[(size_t)row * N + col]       = make_float2(f0, f1);
                *(float2*)&Cf[(size_t)(row + 8) * N + col] = make_float2(f2, f3);
            } else {
                *(uint32_t*)&Ch[(size_t)row * N + col]       = packh2(f0, f1);
                *(uint32_t*)&Ch[(size_t)(row + 8) * N + col] = packh2(f2, f3);
            }
        }
    }
}

// ---------------------------------------------------------------------------
// V transpose: g_v fp16 [tok][DM] -> fp16 [b][h][d][s]
// ---------------------------------------------------------------------------
__global__ __launch_bounds__(256)
void vtrans()
{
    __shared__ __half sm[64][70];
    const int tid = threadIdx.x;
    const int s0 = blockIdx.x * 64, h = blockIdx.y, b = blockIdx.z;
#pragma unroll
    for (int i = 0; i < 16; i++) {
        int lin = tid + i * 256;
        int rr = lin >> 6, d = lin & 63;
        sm[rr][d] = g_v[(size_t)(b * SEQ + s0 + rr) * DM + h * 64 + d];
    }
    __syncthreads();
#pragma unroll
    for (int i = 0; i < 16; i++) {
        int lin = tid + i * 256;
        int dd = lin >> 6, ss = lin & 63;
        size_t o = ((size_t)((b * NH + h) * 64 + dd)) * SEQ + s0 + ss;
        g_vt[o] = sm[ss][dd];
    }
}

// ---------------------------------------------------------------------------
// zdenom: Z = 1/sum_h e_h; stores e_h (fp16) to g_E[b][h][q][k]
// 3-stage cp.async, single sync per head.
// ---------------------------------------------------------------------------
namespace {
constexpr int Z_QT    = 18432;                 // Q tile 128 x 144B
constexpr int Z_KT    = 9216;                  // K tile 64 x 144B
constexpr int Z_STAGE = Z_QT + Z_KT;           // 27648
constexpr int Z_SMEM  = 3 * Z_STAGE;           // 82944
}

__global__ __launch_bounds__(256)
void zdenom_mma()
{
    extern __shared__ __align__(16) char smem[];
    const uint32_t sb = smem_u32(smem);
    const int tid = threadIdx.x, lane = tid & 31, wid = tid >> 5;
    const int r = lane >> 2, c = lane & 3;
    const int b = blockIdx.z, q0 = blockIdx.y * 128, k0 = blockIdx.x * 64;

    auto issue = [&](int h, int s) {
        const uint32_t base = sb + s * Z_STAGE;
#pragma unroll
        for (int i = 0; i < 4; i++) {          // Q: 128 rows x 8 chunks
            int idx = tid + i * 256;
            int rr = idx >> 3, cc = idx & 7;
            cp16(base + rr * 144 + cc * 16,
                 g_q + (size_t)(b * SEQ + q0 + rr) * DM + h * 64 + cc * 8);
        }
#pragma unroll
        for (int i = 0; i < 2; i++) {          // K: 64 rows x 8 chunks
            int idx = tid + i * 256;
            int rr = idx >> 3, cc = idx & 7;
            cp16(base + Z_QT + rr * 144 + cc * 16,
                 g_k + (size_t)(b * SEQ + k0 + rr) * DM + h * 64 + cc * 8);
        }
        cp_commit();
    };

    issue(0, 0);
    issue(1, 1);

    float z[8][4];
#pragma unroll
    for (int i = 0; i < 8; i++)
#pragma unroll
        for (int j = 0; j < 4; j++) z[i][j] = 0.f;

    for (int h = 0; h < NH; h++) {
        if (h == NH - 1) cp_wait<0>(); else cp_wait<1>();
        __syncthreads();
        if (h + 2 < NH) issue(h + 2, (h + 2) % 3);
        const char* st = smem + (h % 3) * Z_STAGE;
        const uint32_t* Q32 = (const uint32_t*)(st);
        const uint32_t* K32 = (const uint32_t*)(st + Z_QT);

        float sc[8][4];
#pragma unroll
        for (int i = 0; i < 8; i++)
#pragma unroll
            for (int j = 0; j < 4; j++) sc[i][j] = 0.f;

#pragma unroll
        for (int kk = 0; kk < 4; kk++) {
            uint32_t aq[4];
            {
                int row = wid * 16 + r;
                int w0 = row * 36 + kk * 8 + c;
                aq[0] = Q32[w0];     aq[1] = Q32[w0 + 288];
                aq[2] = Q32[w0 + 4]; aq[3] = Q32[w0 + 292];
            }
#pragma unroll
            for (int nt = 0; nt < 8; nt++) {
                uint32_t bk[2];
                int rn = nt * 8 + r;
                int w0 = rn * 36 + kk * 8 + c;
                bk[0] = K32[w0]; bk[1] = K32[w0 + 4];
                mma16816(sc[nt], aq, bk);
            }
        }

#pragma unroll
        for (int i = 0; i < 8; i++)
#pragma unroll
            for (int j = 0; j < 4; j++) {
                sc[i][j] = ex2(sc[i][j] * SCLOG2E);
                z[i][j] += sc[i][j];
            }
        {
            size_t eb = ((size_t)((b * NH + h) * SEQ) + q0 + wid * 16 + r) * SEQ + k0;
#pragma unroll
            for (int nt = 0; nt < 8; nt++) {
                *(uint32_t*)&g_E[eb + nt * 8 + 2 * c] = packh2(sc[nt][0], sc[nt][1]);
                *(uint32_t*)&g_E[eb + (size_t)8 * SEQ + nt * 8 + 2 * c] =
                    packh2(sc[nt][2], sc[nt][3]);
            }
        }
    }

#pragma unroll
    for (int nt = 0; nt < 8; nt++) {
        int q = q0 + wid * 16 + r;
        int col = k0 + nt * 8 + 2 * c;
        *(float2*)&g_Z[(size_t)(b * SEQ + q) * SEQ + col] =
            make_float2(frcp(z[nt][0]), frcp(z[nt][1]));
        *(float2*)&g_Z[(size_t)(b * SEQ + q + 8) * SEQ + col] =
            make_float2(frcp(z[nt][2]), frcp(z[nt][3]));
    }
}

// ---------------------------------------------------------------------------
// attn (PV only): p = E .* rz (half2 mul); acc += p @ V
// 3-stage cp.async, single sync per k-tile.
// ---------------------------------------------------------------------------
namespace {
constexpr int AE_T    = 18432;                 // E tile 128 x 144B
constexpr int AV_T    = 9216;                  // V tile 64 x 144B
constexpr int A_STAGE = AE_T + AV_T;           // 27648
constexpr int A_SMEM  = 3 * A_STAGE;           // 82944
}

__global__ __launch_bounds__(256)
void attn_mma()
{
    extern __shared__ __align__(16) char smem[];
    const uint32_t sb = smem_u32(smem);
    const int tid = threadIdx.x, lane = tid & 31, wid = tid >> 5;
    const int r = lane >> 2, c = lane & 3;
    const int b = blockIdx.z, h = blockIdx.y, q0 = blockIdx.x * 128;
    const int hc = h * 64;
    const __half* Eb = g_E + (size_t)(b * NH + h) * SEQ * SEQ;

    auto issue = [&](int kt, int s) {
        const uint32_t base = sb + s * A_STAGE;
#pragma unroll
        for (int i = 0; i < 4; i++) {        // E: 128 rows x 8 chunks
            int idx = tid + i * 256;
            int rr = idx >> 3, cc = idx & 7;
            cp16(base + rr * 144 + cc * 16,
                 Eb + (size_t)(q0 + rr) * SEQ + kt * 64 + cc * 8);
        }
#pragma unroll
        for (int i = 0; i < 2; i++) {        // V: 64 rows x 8 chunks
            int idx = tid + i * 256;
            int r2 = idx >> 3, cc = idx & 7;
            cp16(base + AE_T + r2 * 144 + cc * 16,
                 g_vt + (size_t)((b * NH + h) * 64 + r2) * SEQ + kt * 64 + cc * 8);
        }
        cp_commit();
    };

    issue(0, 0);
    issue(1, 1);

    float acc[8][4];
#pragma unroll
    for (int i = 0; i < 8; i++)
#pragma unroll
        for (int j = 0; j < 4; j++) acc[i][j] = 0.f;

    const int KT = SEQ / 64;   // 32
    for (int kt = 0; kt < KT; kt++) {
        uint32_t rzh[4][4];
        {
            const float* Z0 = g_Z + (size_t)(b * SEQ + q0 + wid * 16 + r) * SEQ
                              + kt * 64 + 2 * c;
            const float* Z1 = Z0 + (size_t)8 * SEQ;
#pragma unroll
            for (int kk = 0; kk < 4; kk++) {
                float2 a0 = *(const float2*)(Z0 + kk * 16);
                float2 a1 = *(const float2*)(Z0 + kk * 16 + 8);
                float2 a2 = *(const float2*)(Z1 + kk * 16);
                float2 a3 = *(const float2*)(Z1 + kk * 16 + 8);
                rzh[kk][0] = packh2(a0.x, a0.y);
                rzh[kk][1] = packh2(a1.x, a1.y);
                rzh[kk][2] = packh2(a2.x, a2.y);
                rzh[kk][3] = packh2(a3.x, a3.y);
            }
        }
        if (kt == KT - 1) cp_wait<0>(); else cp_wait<1>();
        __syncthreads();
        if (kt + 2 < KT) issue(kt + 2, (kt + 2) % 3);
        const char* st = smem + (kt % 3) * A_STAGE;
        const uint32_t* E32 = (const uint32_t*)(st);
        const uint32_t* V32 = (const uint32_t*)(st + AE_T);

#pragma unroll
        for (int kk = 0; kk < 4; kk++) {
            uint32_t ap[4];
            {
                int w0 = (wid * 16 + r) * 36 + kk * 8 + c;
                ap[0] = hmul2u(E32[w0],       rzh[kk][0]);   // (row,   k)
                ap[1] = hmul2u(E32[w0 + 288], rzh[kk][2]);   // (row+8, k)
                ap[2] = hmul2u(E32[w0 + 4],   rzh[kk][1]);   // (row,   k+8)
                ap[3] = hmul2u(E32[w0 + 292], rzh[kk][3]);   // (row+8, k+8)
            }
#pragma unroll
            for (int dt = 0; dt < 8; dt++) {
                uint32_t bv[2];
                int w1 = (dt * 8 + r) * 36 + kk * 8 + c;
                bv[0] = V32[w1]; bv[1] = V32[w1 + 4];
                mma16816(acc[dt], ap, bv);
            }
        }
    }

    // epilogue: context -> fp16
#pragma unroll
    for (int dt = 0; dt < 8; dt++) {
        int row = b * SEQ + q0 + wid * 16 + r;
        int col = hc + dt * 8 + 2 * c;
        *(uint32_t*)&g_c[(size_t)row * DM + col]       = packh2(acc[dt][0], acc[dt][1]);
        *(uint32_t*)&g_c[(size_t)(row + 8) * DM + col] = packh2(acc[dt][2], acc[dt][3]);
    }
}

// ---------------------------------------------------------------------------
extern "C" void kernel_launch(void* const* d_in, const int* in_sizes, int n_in,
                              void* d_out, int out_size)
{
    (void)in_sizes; (void)n_in; (void)out_size;
    const float* x  = (const float*)d_in[0];
    const float* Wq = (const float*)d_in[1];
    const float* bq = (const float*)d_in[2];
    const float* Wk = (const float*)d_in[3];
    const float* bk = (const float*)d_in[4];
    const float* Wv = (const float*)d_in[5];
    const float* bv = (const float*)d_in[6];
    const float* Wo = (const float*)d_in[7];
    const float* bo = (const float*)d_in[8];
    float* out = (float*)d_out;

    __half *xp, *wp, *qp, *kp, *vp, *cp;
    cudaGetSymbolAddress((void**)&xp, g_x);
    cudaGetSymbolAddress((void**)&wp, g_w);
    cudaGetSymbolAddress((void**)&qp, g_q);
    cudaGetSymbolAddress((void**)&kp, g_k);
    cudaGetSymbolAddress((void**)&vp, g_v);
    cudaGetSymbolAddress((void**)&cp, g_c);

    cudaFuncSetAttribute(gemm_mma<0>, cudaFuncAttributeMaxDynamicSharedMemorySize, G_SMEM);
    cudaFuncSetAttribute(gemm_mma<1>, cudaFuncAttributeMaxDynamicSharedMemorySize, G_SMEM);
    cudaFuncSetAttribute(zdenom_mma,  cudaFuncAttributeMaxDynamicSharedMemorySize, Z_SMEM);
    cudaFuncSetAttribute(attn_mma,    cudaFuncAttributeMaxDynamicSharedMemorySize, A_SMEM);

    const int NX = NTOK * DM;   // 4M
    const int NW = DM * DM;     // 1M
    cvt_all<<<dim3(NX / 1024, 2), 256>>>(x, Wq, Wk, Wv, Wo, xp, wp);

    // fused Q/K/V projections (grid.z selects weight/bias/output)
    gemm_mma<1><<<dim3(DM / 128, NTOK / 128, 3), 256, G_SMEM>>>(
        xp, wp + 0 * NW, wp + 1 * NW, wp + 2 * NW,
        bq, bk, bv, nullptr, qp, kp, vp, NTOK, DM, DM);

    zdenom_mma<<<dim3(SEQ / 64, SEQ / 128, BT), 256, Z_SMEM>>>();

    vtrans<<<dim3(SEQ / 64, NH, BT), 256>>>();

    attn_mma<<<dim3(SEQ / 128, NH, BT), 256, A_SMEM>>>();

    gemm_mma<0><<<dim3(DM / 128, NTOK / 128, 1), 256, G_SMEM>>>(
        cp, wp + 3 * NW, wp + 3 * NW, wp + 3 * NW,
        bo, bo, bo, out, nullptr, nullptr, nullptr, NTOK, DM, DM);
}

// round 14
// speedup vs baseline: 1.9700x; 1.0440x over previous
#include <cuda_runtime.h>
#include <cuda_bf16.h>
#include <cuda_fp16.h>
#include <cstdint>

namespace {
constexpr int SEQ = 2048;
constexpr int BT  = 2;
constexpr int DM  = 1024;
constexpr int NH  = 16;
constexpr int NTOK = BT * SEQ;     // 4096
constexpr float SCLOG2E = 0.125f * 1.4426950408889634f;  // scale * log2(e)
}

// ---------------- device scratch (allocation-free) ----------------
__device__ __half g_q [NTOK * DM];                   // Q, fp16
__device__ __half g_k [NTOK * DM];                   // K, fp16
__device__ __half g_v [NTOK * DM];                   // V, fp16 [tok][DM]
__device__ __half g_vt[NTOK * DM];                   // [b][h][d][s], fp16
__device__ __half g_c [NTOK * DM];                   // context, fp16
__device__ float  g_Z [BT * SEQ * SEQ];              // reciprocal denom
__device__ __half g_E [(size_t)BT * NH * SEQ * SEQ]; // exp(scores), [b][h][q][k]
__device__ __half g_x [NTOK * DM];                   // x, fp16
__device__ __half g_w [4][DM * DM];                  // weights, fp16

// ---------------- tiny PTX helpers (sm_103-safe) ----------------
__device__ __forceinline__ uint32_t smem_u32(const void* p) {
    uint32_t a;
    asm("{ .reg .u64 t; cvta.to.shared.u64 t, %1; cvt.u32.u64 %0, t; }" : "=r"(a) : "l"(p));
    return a;
}
__device__ __forceinline__ void cp16(uint32_t dst, const void* src) {
    asm volatile("cp.async.cg.shared.global [%0], [%1], 16;" :: "r"(dst), "l"(src) : "memory");
}
__device__ __forceinline__ void cp_commit() {
    asm volatile("cp.async.commit_group;" ::: "memory");
}
template <int N> __device__ __forceinline__ void cp_wait() {
    asm volatile("cp.async.wait_group %0;" :: "n"(N) : "memory");
}
__device__ __forceinline__ void mma16816(float* d, const uint32_t* a, const uint32_t* b) {
    asm volatile(
        "mma.sync.aligned.m16n8k16.row.col.f32.f16.f16.f32 "
        "{%0,%1,%2,%3}, {%4,%5,%6,%7}, {%8,%9}, {%0,%1,%2,%3};"
        : "+f"(d[0]), "+f"(d[1]), "+f"(d[2]), "+f"(d[3])
        : "r"(a[0]), "r"(a[1]), "r"(a[2]), "r"(a[3]), "r"(b[0]), "r"(b[1]));
}
// ldmatrix x4: 4 8x8 b16 matrices
__device__ __forceinline__ void ldsm4(uint32_t* r, uint32_t a) {
    asm volatile("ldmatrix.sync.aligned.m8n8.x4.shared.b16 {%0,%1,%2,%3}, [%4];"
        : "=r"(r[0]), "=r"(r[1]), "=r"(r[2]), "=r"(r[3]) : "r"(a));
}
__device__ __forceinline__ float ex2(float x) {
    float y; asm("ex2.approx.ftz.f32 %0, %1;" : "=f"(y) : "f"(x)); return y;
}
__device__ __forceinline__ float frcp(float x) {
    float y; asm("rcp.approx.ftz.f32 %0, %1;" : "=f"(y) : "f"(x)); return y;
}
// pack two fp32 -> f16x2 reg: low half = `lo` (lower column index)
__device__ __forceinline__ uint32_t packh2(float lo, float hi) {
    uint32_t r; asm("cvt.rn.f16x2.f32 %0, %1, %2;" : "=r"(r) : "f"(hi), "f"(lo)); return r;
}
__device__ __forceinline__ uint32_t hmul2u(uint32_t a, uint32_t b) {
    __half2 r = __hmul2(*(const __half2*)&a, *(const __half2*)&b);
    return *(uint32_t*)&r;
}

// ---------------------------------------------------------------------------
// One launch: x (y=0) and all 4 weights (y=1) -> fp16
// ---------------------------------------------------------------------------
__global__ __launch_bounds__(256)
void cvt_all(const float* __restrict__ x,
             const float* __restrict__ W0, const float* __restrict__ W1,
             const float* __restrict__ W2, const float* __restrict__ W3,
             __half* __restrict__ xo, __half* __restrict__ wo)
{
    int i = (blockIdx.x * 256 + threadIdx.x) * 4;   // 0 .. 4M
    const float* in;
    __half* out;
    if (blockIdx.y == 0) { in = x; out = xo; }
    else {
        int w = i >> 20;                             // NW = 1<<20
        in  = (w == 0) ? W0 : (w == 1) ? W1 : (w == 2) ? W2 : W3;
        in -= (size_t)w << 20;                       // rebase so in+i is correct
        out = wo;
    }
    float4 v = *(const float4*)(in + i);
    ushort4 o;
    o.x = __half_as_ushort(__float2half_rn(v.x));
    o.y = __half_as_ushort(__float2half_rn(v.y));
    o.z = __half_as_ushort(__float2half_rn(v.z));
    o.w = __half_as_ushort(__float2half_rn(v.w));
    *(ushort4*)((unsigned short*)out + i) = o;
}

// ---------------------------------------------------------------------------
// HMMA fp16 GEMM: C = A * B^T + bias. grid.z selects (B, bias, out) triple.
// CTA 128x128, BK=64, 8 warps, 3-stage cp.async, ldmatrix fragments.
// OUT: 0 = fp32, 1 = fp16
// ---------------------------------------------------------------------------
namespace {
constexpr int G_RSB   = 144;
constexpr int G_TILE  = 128 * G_RSB;       // 18432
constexpr int G_STAGE = 2 * G_TILE;        // 36864 (A, B)
constexpr int G_SMEM  = 3 * G_STAGE;       // 110592
}

template <int OUT>
__global__ __launch_bounds__(256, 2)
void gemm_mma(const __half* __restrict__ A,
              const __half* __restrict__ B0, const __half* __restrict__ B1,
              const __half* __restrict__ B2,
              const float* __restrict__ bias0, const float* __restrict__ bias1,
              const float* __restrict__ bias2,
              float* __restrict__ Cf,
              __half* __restrict__ Ch0, __half* __restrict__ Ch1,
              __half* __restrict__ Ch2,
              int M, int N, int K)
{
    extern __shared__ __align__(16) char smem[];
    const uint32_t sb = smem_u32(smem);
    const int tid = threadIdx.x, lane = tid & 31, wid = tid >> 5;
    const int wm = wid >> 2, wn = wid & 3;
    const int r = lane >> 2, c = lane & 3;
    const int m0 = blockIdx.y * 128, n0 = blockIdx.x * 128;
    const int z = blockIdx.z;
    const __half* B = (z == 0) ? B0 : (z == 1) ? B1 : B2;
    const float* bias = (z == 0) ? bias0 : (z == 1) ? bias1 : bias2;
    __half* Ch = (z == 0) ? Ch0 : (z == 1) ? Ch1 : Ch2;
    const int KT = K / 64;

    // ldmatrix lane-address components
    const int la = lane & 15;                          // A-row within 16
    const int ka = (lane >> 4) * 16;                   // A 16B half select
    const int lb = (lane & 7) + ((lane >> 4) & 1) * 8; // B-row within 16
    const int kb = ((lane >> 3) & 1) * 16;             // B 16B half select

    float acc[4][4][4];
#pragma unroll
    for (int i = 0; i < 4; i++)
#pragma unroll
        for (int j = 0; j < 4; j++)
#pragma unroll
            for (int q = 0; q < 4; q++) acc[i][j][q] = 0.f;

    auto issue = [&](int kt, int s) {
        const int k0 = kt * 64;
#pragma unroll
        for (int a = 0; a < 2; a++) {
            const __half* g = (a == 0) ? A : B;
            const int rbase = (a == 0) ? m0 : n0;
            const uint32_t dstb = sb + s * G_STAGE + a * G_TILE;
#pragma unroll
            for (int i = 0; i < 4; i++) {
                int idx = tid + i * 256;
                int rr = idx >> 3, cc = idx & 7;
                cp16(dstb + rr * G_RSB + cc * 16,
                     g + (size_t)(rbase + rr) * K + k0 + cc * 8);
            }
        }
        cp_commit();
    };

    issue(0, 0);
    issue(1, 1);

    for (int kt = 0; kt < KT; kt++) {
        if (kt == KT - 1) cp_wait<0>(); else cp_wait<1>();
        __syncthreads();
        if (kt + 2 < KT) issue(kt + 2, (kt + 2) % 3);
        const uint32_t st = sb + (kt % 3) * G_STAGE;

#pragma unroll
        for (int kk = 0; kk < 4; kk++) {
            uint32_t ah[4][4], bp[2][4];
            const uint32_t aoff = st + (uint32_t)(wm * 64 + la) * G_RSB + kk * 32 + ka;
#pragma unroll
            for (int mt = 0; mt < 4; mt++)
                ldsm4(ah[mt], aoff + mt * (16 * G_RSB));
            const uint32_t boff = st + G_TILE
                                + (uint32_t)(wn * 32 + lb) * G_RSB + kk * 32 + kb;
#pragma unroll
            for (int p = 0; p < 2; p++)
                ldsm4(bp[p], boff + p * (16 * G_RSB));
#pragma unroll
            for (int mt = 0; mt < 4; mt++)
#pragma unroll
                for (int nt = 0; nt < 4; nt++)
                    mma16816(acc[mt][nt], ah[mt], &bp[nt >> 1][(nt & 1) * 2]);
        }
    }

#pragma unroll
    for (int mt = 0; mt < 4; mt++) {
#pragma unroll
        for (int nt = 0; nt < 4; nt++) {
            int row = m0 + wm * 64 + mt * 16 + r;
            int col = n0 + wn * 32 + nt * 8 + 2 * c;
            float b0 = bias[col], b1 = bias[col + 1];
            float f0 = acc[mt][nt][0] + b0, f1 = acc[mt][nt][1] + b1;
            float f2 = acc[mt][nt][2] + b0, f3 = acc[mt][nt][3] + b1;
            if (OUT == 0) {
                *(float2*)&Cf[(size_t)row * N + col]       = make_float2(f0, f1);
                *(float2*)&Cf[(size_t)(row + 8) * N + col] = make_float2(f2, f3);
            } else {
                *(uint32_t*)&Ch[(size_t)row * N + col]       = packh2(f0, f1);
                *(uint32_t*)&Ch[(size_t)(row + 8) * N + col] = packh2(f2, f3);
            }
        }
    }
}

// ---------------------------------------------------------------------------
// V transpose: g_v fp16 [tok][DM] -> fp16 [b][h][d][s]
// ---------------------------------------------------------------------------
__global__ __launch_bounds__(256)
void vtrans()
{
    __shared__ __half sm[64][70];
    const int tid = threadIdx.x;
    const int s0 = blockIdx.x * 64, h = blockIdx.y, b = blockIdx.z;
#pragma unroll
    for (int i = 0; i < 16; i++) {
        int lin = tid + i * 256;
        int rr = lin >> 6, d = lin & 63;
        sm[rr][d] = g_v[(size_t)(b * SEQ + s0 + rr) * DM + h * 64 + d];
    }
    __syncthreads();
#pragma unroll
    for (int i = 0; i < 16; i++) {
        int lin = tid + i * 256;
        int dd = lin >> 6, ss = lin & 63;
        size_t o = ((size_t)((b * NH + h) * 64 + dd)) * SEQ + s0 + ss;
        g_vt[o] = sm[ss][dd];
    }
}

// ---------------------------------------------------------------------------
// zdenom: Z = 1/sum_h e_h; stores e_h (fp16) to g_E[b][h][q][k]
// 3-stage cp.async, single sync per head, ldmatrix fragments.
// ---------------------------------------------------------------------------
namespace {
constexpr int Z_QT    = 18432;                 // Q tile 128 x 144B
constexpr int Z_KT    = 9216;                  // K tile 64 x 144B
constexpr int Z_STAGE = Z_QT + Z_KT;           // 27648
constexpr int Z_SMEM  = 3 * Z_STAGE;           // 82944
}

__global__ __launch_bounds__(256)
void zdenom_mma()
{
    extern __shared__ __align__(16) char smem[];
    const uint32_t sb = smem_u32(smem);
    const int tid = threadIdx.x, lane = tid & 31, wid = tid >> 5;
    const int r = lane >> 2, c = lane & 3;
    const int b = blockIdx.z, q0 = blockIdx.y * 128, k0 = blockIdx.x * 64;

    const int la = lane & 15;
    const int ka = (lane >> 4) * 16;
    const int lb = (lane & 7) + ((lane >> 4) & 1) * 8;
    const int kb = ((lane >> 3) & 1) * 16;

    auto issue = [&](int h, int s) {
        const uint32_t base = sb + s * Z_STAGE;
#pragma unroll
        for (int i = 0; i < 4; i++) {          // Q: 128 rows x 8 chunks
            int idx = tid + i * 256;
            int rr = idx >> 3, cc = idx & 7;
            cp16(base + rr * 144 + cc * 16,
                 g_q + (size_t)(b * SEQ + q0 + rr) * DM + h * 64 + cc * 8);
        }
#pragma unroll
        for (int i = 0; i < 2; i++) {          // K: 64 rows x 8 chunks
            int idx = tid + i * 256;
            int rr = idx >> 3, cc = idx & 7;
            cp16(base + Z_QT + rr * 144 + cc * 16,
                 g_k + (size_t)(b * SEQ + k0 + rr) * DM + h * 64 + cc * 8);
        }
        cp_commit();
    };

    issue(0, 0);
    issue(1, 1);

    float z[8][4];
#pragma unroll
    for (int i = 0; i < 8; i++)
#pragma unroll
        for (int j = 0; j < 4; j++) z[i][j] = 0.f;

    for (int h = 0; h < NH; h++) {
        if (h == NH - 1) cp_wait<0>(); else cp_wait<1>();
        __syncthreads();
        if (h + 2 < NH) issue(h + 2, (h + 2) % 3);
        const uint32_t st = sb + (h % 3) * Z_STAGE;

        float sc[8][4];
#pragma unroll
        for (int i = 0; i < 8; i++)
#pragma unroll
            for (int j = 0; j < 4; j++) sc[i][j] = 0.f;

#pragma unroll
        for (int kk = 0; kk < 4; kk++) {
            uint32_t aq[4], kp[4][4];
            ldsm4(aq, st + (uint32_t)(wid * 16 + la) * 144 + kk * 32 + ka);
            const uint32_t koff = st + Z_QT + (uint32_t)lb * 144 + kk * 32 + kb;
#pragma unroll
            for (int p = 0; p < 4; p++)
                ldsm4(kp[p], koff + p * (16 * 144));
#pragma unroll
            for (int nt = 0; nt < 8; nt++)
                mma16816(sc[nt], aq, &kp[nt >> 1][(nt & 1) * 2]);
        }

#pragma unroll
        for (int i = 0; i < 8; i++)
#pragma unroll
            for (int j = 0; j < 4; j++) {
                sc[i][j] = ex2(sc[i][j] * SCLOG2E);
                z[i][j] += sc[i][j];
            }
        {
            size_t eb = ((size_t)((b * NH + h) * SEQ) + q0 + wid * 16 + r) * SEQ + k0;
#pragma unroll
            for (int nt = 0; nt < 8; nt++) {
                *(uint32_t*)&g_E[eb + nt * 8 + 2 * c] = packh2(sc[nt][0], sc[nt][1]);
                *(uint32_t*)&g_E[eb + (size_t)8 * SEQ + nt * 8 + 2 * c] =
                    packh2(sc[nt][2], sc[nt][3]);
            }
        }
    }

#pragma unroll
    for (int nt = 0; nt < 8; nt++) {
        int q = q0 + wid * 16 + r;
        int col = k0 + nt * 8 + 2 * c;
        *(float2*)&g_Z[(size_t)(b * SEQ + q) * SEQ + col] =
            make_float2(frcp(z[nt][0]), frcp(z[nt][1]));
        *(float2*)&g_Z[(size_t)(b * SEQ + q + 8) * SEQ + col] =
            make_float2(frcp(z[nt][2]), frcp(z[nt][3]));
    }
}

// ---------------------------------------------------------------------------
// attn (PV only): p = E .* rz (half2 mul); acc += p @ V
// 3-stage cp.async, single sync per k-tile, ldmatrix fragments.
// ---------------------------------------------------------------------------
namespace {
constexpr int AE_T    = 18432;                 // E tile 128 x 144B
constexpr int AV_T    = 9216;                  // V tile 64 x 144B
constexpr int A_STAGE = AE_T + AV_T;           // 27648
constexpr int A_SMEM  = 3 * A_STAGE;           // 82944
}

__global__ __launch_bounds__(256)
void attn_mma()
{
    extern __shared__ __align__(16) char smem[];
    const uint32_t sb = smem_u32(smem);
    const int tid = threadIdx.x, lane = tid & 31, wid = tid >> 5;
    const int r = lane >> 2, c = lane & 3;
    const int b = blockIdx.z, h = blockIdx.y, q0 = blockIdx.x * 128;
    const int hc = h * 64;
    const __half* Eb = g_E + (size_t)(b * NH + h) * SEQ * SEQ;

    const int la = lane & 15;
    const int ka = (lane >> 4) * 16;
    const int lb = (lane & 7) + ((lane >> 4) & 1) * 8;
    const int kb = ((lane >> 3) & 1) * 16;

    auto issue = [&](int kt, int s) {
        const uint32_t base = sb + s * A_STAGE;
#pragma unroll
        for (int i = 0; i < 4; i++) {        // E: 128 rows x 8 chunks
            int idx = tid + i * 256;
            int rr = idx >> 3, cc = idx & 7;
            cp16(base + rr * 144 + cc * 16,
                 Eb + (size_t)(q0 + rr) * SEQ + kt * 64 + cc * 8);
        }
#pragma unroll
        for (int i = 0; i < 2; i++) {        // V: 64 rows x 8 chunks
            int idx = tid + i * 256;
            int r2 = idx >> 3, cc = idx & 7;
            cp16(base + AE_T + r2 * 144 + cc * 16,
                 g_vt + (size_t)((b * NH + h) * 64 + r2) * SEQ + kt * 64 + cc * 8);
        }
        cp_commit();
    };

    issue(0, 0);
    issue(1, 1);

    float acc[8][4];
#pragma unroll
    for (int i = 0; i < 8; i++)
#pragma unroll
        for (int j = 0; j < 4; j++) acc[i][j] = 0.f;

    const int KT = SEQ / 64;   // 32
    for (int kt = 0; kt < KT; kt++) {
        uint32_t rzh[4][4];
        {
            const float* Z0 = g_Z + (size_t)(b * SEQ + q0 + wid * 16 + r) * SEQ
                              + kt * 64 + 2 * c;
            const float* Z1 = Z0 + (size_t)8 * SEQ;
#pragma unroll
            for (int kk = 0; kk < 4; kk++) {
                float2 a0 = *(const float2*)(Z0 + kk * 16);
                float2 a1 = *(const float2*)(Z0 + kk * 16 + 8);
                float2 a2 = *(const float2*)(Z1 + kk * 16);
                float2 a3 = *(const float2*)(Z1 + kk * 16 + 8);
                rzh[kk][0] = packh2(a0.x, a0.y);
                rzh[kk][1] = packh2(a1.x, a1.y);
                rzh[kk][2] = packh2(a2.x, a2.y);
                rzh[kk][3] = packh2(a3.x, a3.y);
            }
        }
        if (kt == KT - 1) cp_wait<0>(); else cp_wait<1>();
        __syncthreads();
        if (kt + 2 < KT) issue(kt + 2, (kt + 2) % 3);
        const uint32_t st = sb + (kt % 3) * A_STAGE;

#pragma unroll
        for (int kk = 0; kk < 4; kk++) {
            uint32_t ap[4];
            {
                uint32_t ef[4];
                ldsm4(ef, st + (uint32_t)(wid * 16 + la) * 144 + kk * 32 + ka);
                ap[0] = hmul2u(ef[0], rzh[kk][0]);   // (row,   k)
                ap[1] = hmul2u(ef[1], rzh[kk][2]);   // (row+8, k)
                ap[2] = hmul2u(ef[2], rzh[kk][1]);   // (row,   k+8)
                ap[3] = hmul2u(ef[3], rzh[kk][3]);   // (row+8, k+8)
            }
            uint32_t vp[4][4];
            const uint32_t voff = st + AE_T + (uint32_t)lb * 144 + kk * 32 + kb;
#pragma unroll
            for (int p = 0; p < 4; p++)
                ldsm4(vp[p], voff + p * (16 * 144));
#pragma unroll
            for (int dt = 0; dt < 8; dt++)
                mma16816(acc[dt], ap, &vp[dt >> 1][(dt & 1) * 2]);
        }
    }

    // epilogue: context -> fp16
#pragma unroll
    for (int dt = 0; dt < 8; dt++) {
        int row = b * SEQ + q0 + wid * 16 + r;
        int col = hc + dt * 8 + 2 * c;
        *(uint32_t*)&g_c[(size_t)row * DM + col]       = packh2(acc[dt][0], acc[dt][1]);
        *(uint32_t*)&g_c[(size_t)(row + 8) * DM + col] = packh2(acc[dt][2], acc[dt][3]);
    }
}

// ---------------------------------------------------------------------------
extern "C" void kernel_launch(void* const* d_in, const int* in_sizes, int n_in,
                              void* d_out, int out_size)
{
    (void)in_sizes; (void)n_in; (void)out_size;
    const float* x  = (const float*)d_in[0];
    const float* Wq = (const float*)d_in[1];
    const float* bq = (const float*)d_in[2];
    const float* Wk = (const float*)d_in[3];
    const float* bk = (const float*)d_in[4];
    const float* Wv = (const float*)d_in[5];
    const float* bv = (const float*)d_in[6];
    const float* Wo = (const float*)d_in[7];
    const float* bo = (const float*)d_in[8];
    float* out = (float*)d_out;

    __half *xp, *wp, *qp, *kp, *vp, *cp;
    cudaGetSymbolAddress((void**)&xp, g_x);
    cudaGetSymbolAddress((void**)&wp, g_w);
    cudaGetSymbolAddress((void**)&qp, g_q);
    cudaGetSymbolAddress((void**)&kp, g_k);
    cudaGetSymbolAddress((void**)&vp, g_v);
    cudaGetSymbolAddress((void**)&cp, g_c);

    cudaFuncSetAttribute(gemm_mma<0>, cudaFuncAttributeMaxDynamicSharedMemorySize, G_SMEM);
    cudaFuncSetAttribute(gemm_mma<1>, cudaFuncAttributeMaxDynamicSharedMemorySize, G_SMEM);
    cudaFuncSetAttribute(zdenom_mma,  cudaFuncAttributeMaxDynamicSharedMemorySize, Z_SMEM);
    cudaFuncSetAttribute(attn_mma,    cudaFuncAttributeMaxDynamicSharedMemorySize, A_SMEM);

    const int NX = NTOK * DM;   // 4M
    const int NW = DM * DM;     // 1M
    cvt_all<<<dim3(NX / 1024, 2), 256>>>(x, Wq, Wk, Wv, Wo, xp, wp);

    // fused Q/K/V projections (grid.z selects weight/bias/output)
    gemm_mma<1><<<dim3(DM / 128, NTOK / 128, 3), 256, G_SMEM>>>(
        xp, wp + 0 * NW, wp + 1 * NW, wp + 2 * NW,
        bq, bk, bv, nullptr, qp, kp, vp, NTOK, DM, DM);

    zdenom_mma<<<dim3(SEQ / 64, SEQ / 128, BT), 256, Z_SMEM>>>();

    vtrans<<<dim3(SEQ / 64, NH, BT), 256>>>();

    attn_mma<<<dim3(SEQ / 128, NH, BT), 256, A_SMEM>>>();

    gemm_mma<0><<<dim3(DM / 128, NTOK / 128, 1), 256, G_SMEM>>>(
        cp, wp + 3 * NW, wp + 3 * NW, wp + 3 * NW,
        bo, bo, bo, out, nullptr, nullptr, nullptr, NTOK, DM, DM);
}

// round 16
// speedup vs baseline: 2.1751x; 1.1041x over previous
#include <cuda_runtime.h>
#include <cuda_bf16.h>
#include <cuda_fp16.h>
#include <cstdint>

namespace {
constexpr int SEQ = 2048;
constexpr int BT  = 2;
constexpr int DM  = 1024;
constexpr int NH  = 16;
constexpr int NTOK = BT * SEQ;     // 4096
constexpr float SCLOG2E = 0.125f * 1.4426950408889634f;  // scale * log2(e)
}

// ---------------- device scratch (allocation-free) ----------------
__device__ __half g_q [NTOK * DM];                   // Q, fp16
__device__ __half g_k [NTOK * DM];                   // K, fp16
__device__ __half g_vt[NTOK * DM];                   // V, [b][h][d][s], fp16
__device__ __half g_c [NTOK * DM];                   // context, fp16
__device__ __half g_rz[(size_t)BT * SEQ * SEQ];      // reciprocal denom, fp16
__device__ __half g_E [(size_t)BT * NH * SEQ * SEQ]; // exp(scores), [b][h][q][k]
__device__ __half g_x [NTOK * DM];                   // x, fp16
__device__ __half g_w [4][DM * DM];                  // weights, fp16

// ---------------- tiny PTX helpers (sm_103-safe) ----------------
__device__ __forceinline__ uint32_t smem_u32(const void* p) {
    uint32_t a;
    asm("{ .reg .u64 t; cvta.to.shared.u64 t, %1; cvt.u32.u64 %0, t; }" : "=r"(a) : "l"(p));
    return a;
}
__device__ __forceinline__ void cp16(uint32_t dst, const void* src) {
    asm volatile("cp.async.cg.shared.global [%0], [%1], 16;" :: "r"(dst), "l"(src) : "memory");
}
__device__ __forceinline__ void cp_commit() {
    asm volatile("cp.async.commit_group;" ::: "memory");
}
template <int N> __device__ __forceinline__ void cp_wait() {
    asm volatile("cp.async.wait_group %0;" :: "n"(N) : "memory");
}
__device__ __forceinline__ void mma16816(float* d, const uint32_t* a, const uint32_t* b) {
    asm volatile(
        "mma.sync.aligned.m16n8k16.row.col.f32.f16.f16.f32 "
        "{%0,%1,%2,%3}, {%4,%5,%6,%7}, {%8,%9}, {%0,%1,%2,%3};"
        : "+f"(d[0]), "+f"(d[1]), "+f"(d[2]), "+f"(d[3])
        : "r"(a[0]), "r"(a[1]), "r"(a[2]), "r"(a[3]), "r"(b[0]), "r"(b[1]));
}
// ldmatrix x4: 4 8x8 b16 matrices
__device__ __forceinline__ void ldsm4(uint32_t* r, uint32_t a) {
    asm volatile("ldmatrix.sync.aligned.m8n8.x4.shared.b16 {%0,%1,%2,%3}, [%4];"
        : "=r"(r[0]), "=r"(r[1]), "=r"(r[2]), "=r"(r[3]) : "r"(a));
}
__device__ __forceinline__ float ex2(float x) {
    float y; asm("ex2.approx.ftz.f32 %0, %1;" : "=f"(y) : "f"(x)); return y;
}
__device__ __forceinline__ float frcp(float x) {
    float y; asm("rcp.approx.ftz.f32 %0, %1;" : "=f"(y) : "f"(x)); return y;
}
// pack two fp32 -> f16x2 reg: low half = `lo` (lower column index)
__device__ __forceinline__ uint32_t packh2(float lo, float hi) {
    uint32_t r; asm("cvt.rn.f16x2.f32 %0, %1, %2;" : "=r"(r) : "f"(hi), "f"(lo)); return r;
}
__device__ __forceinline__ uint32_t hmul2u(uint32_t a, uint32_t b) {
    __half2 r = __hmul2(*(const __half2*)&a, *(const __half2*)&b);
    return *(uint32_t*)&r;
}

// ---------------------------------------------------------------------------
// One launch: x (y=0) and all 4 weights (y=1) -> fp16
// ---------------------------------------------------------------------------
__global__ __launch_bounds__(256)
void cvt_all(const float* __restrict__ x,
             const float* __restrict__ W0, const float* __restrict__ W1,
             const float* __restrict__ W2, const float* __restrict__ W3,
             __half* __restrict__ xo, __half* __restrict__ wo)
{
    int i = (blockIdx.x * 256 + threadIdx.x) * 4;   // 0 .. 4M
    const float* in;
    __half* out;
    if (blockIdx.y == 0) { in = x; out = xo; }
    else {
        int w = i >> 20;                             // NW = 1<<20
        in  = (w == 0) ? W0 : (w == 1) ? W1 : (w == 2) ? W2 : W3;
        in -= (size_t)w << 20;                       // rebase so in+i is correct
        out = wo;
    }
    float4 v = *(const float4*)(in + i);
    ushort4 o;
    o.x = __half_as_ushort(__float2half_rn(v.x));
    o.y = __half_as_ushort(__float2half_rn(v.y));
    o.z = __half_as_ushort(__float2half_rn(v.z));
    o.w = __half_as_ushort(__float2half_rn(v.w));
    *(ushort4*)((unsigned short*)out + i) = o;
}

// ---------------------------------------------------------------------------
// HMMA fp16 GEMM: C = A * B^T + bias. grid.z selects (B, bias, out) triple.
// CTA 128x128, BK=64, 8 warps, 3-stage cp.async, ldmatrix fragments.
// OUT: 0 = fp32 out; 1 = fp16 out, and z==2 writes TRANSPOSED per-head layout
//      (V path: g_vt[(b*NH+h)*64+d][s]) via an smem-staged transpose.
// ---------------------------------------------------------------------------
namespace {
constexpr int G_RSB   = 144;
constexpr int G_TILE  = 128 * G_RSB;       // 18432
constexpr int G_STAGE = 2 * G_TILE;        // 36864 (A, B)
constexpr int G_SMEM  = 3 * G_STAGE;       // 110592
constexpr int T_PAD   = 136;               // transpose staging row stride (halves)
}

template <int OUT>
__global__ __launch_bounds__(256, 2)
void gemm_mma(const __half* __restrict__ A,
              const __half* __restrict__ B0, const __half* __restrict__ B1,
              const __half* __restrict__ B2,
              const float* __restrict__ bias0, const float* __restrict__ bias1,
              const float* __restrict__ bias2,
              float* __restrict__ Cf,
              __half* __restrict__ Ch0, __half* __restrict__ Ch1,
              __half* __restrict__ ChT,
              int M, int N, int K)
{
    extern __shared__ __align__(16) char smem[];
    const uint32_t sb = smem_u32(smem);
    const int tid = threadIdx.x, lane = tid & 31, wid = tid >> 5;
    const int wm = wid >> 2, wn = wid & 3;
    const int r = lane >> 2, c = lane & 3;
    const int m0 = blockIdx.y * 128, n0 = blockIdx.x * 128;
    const int z = blockIdx.z;
    const __half* B = (z == 0) ? B0 : (z == 1) ? B1 : B2;
    const float* bias = (z == 0) ? bias0 : (z == 1) ? bias1 : bias2;
    __half* Ch = (z == 0) ? Ch0 : Ch1;
    const int KT = K / 64;

    // ldmatrix lane-address components
    const int la = lane & 15;                          // A-row within 16
    const int ka = (lane >> 4) * 16;                   // A 16B half select
    const int lb = (lane & 7) + ((lane >> 4) & 1) * 8; // B-row within 16
    const int kb = ((lane >> 3) & 1) * 16;             // B 16B half select

    float acc[4][4][4];
#pragma unroll
    for (int i = 0; i < 4; i++)
#pragma unroll
        for (int j = 0; j < 4; j++)
#pragma unroll
            for (int q = 0; q < 4; q++) acc[i][j][q] = 0.f;

    auto issue = [&](int kt, int s) {
        const int k0 = kt * 64;
#pragma unroll
        for (int a = 0; a < 2; a++) {
            const __half* g = (a == 0) ? A : B;
            const int rbase = (a == 0) ? m0 : n0;
            const uint32_t dstb = sb + s * G_STAGE + a * G_TILE;
#pragma unroll
            for (int i = 0; i < 4; i++) {
                int idx = tid + i * 256;
                int rr = idx >> 3, cc = idx & 7;
                cp16(dstb + rr * G_RSB + cc * 16,
                     g + (size_t)(rbase + rr) * K + k0 + cc * 8);
            }
        }
        cp_commit();
    };

    issue(0, 0);
    issue(1, 1);

    for (int kt = 0; kt < KT; kt++) {
        if (kt == KT - 1) cp_wait<0>(); else cp_wait<1>();
        __syncthreads();
        if (kt + 2 < KT) issue(kt + 2, (kt + 2) % 3);
        const uint32_t st = sb + (kt % 3) * G_STAGE;

#pragma unroll
        for (int kk = 0; kk < 4; kk++) {
            uint32_t ah[4][4], bp[2][4];
            const uint32_t aoff = st + (uint32_t)(wm * 64 + la) * G_RSB + kk * 32 + ka;
#pragma unroll
            for (int mt = 0; mt < 4; mt++)
                ldsm4(ah[mt], aoff + mt * (16 * G_RSB));
            const uint32_t boff = st + G_TILE
                                + (uint32_t)(wn * 32 + lb) * G_RSB + kk * 32 + kb;
#pragma unroll
            for (int p = 0; p < 2; p++)
                ldsm4(bp[p], boff + p * (16 * G_RSB));
#pragma unroll
            for (int mt = 0; mt < 4; mt++)
#pragma unroll
                for (int nt = 0; nt < 4; nt++)
                    mma16816(acc[mt][nt], ah[mt], &bp[nt >> 1][(nt & 1) * 2]);
        }
    }

    if (OUT == 1 && z == 2) {
        // V path: stage fp16 tile transposed in smem [col][token], then write
        // coalesced rows to ChT[(b*NH+h)*64+d][s].
        __syncthreads();                      // pipeline smem now reusable
        __half* ts = (__half*)smem;
#pragma unroll
        for (int mt = 0; mt < 4; mt++) {
#pragma unroll
            for (int nt = 0; nt < 4; nt++) {
                int lrow = wm * 64 + mt * 16 + r;
                int lcol = wn * 32 + nt * 8 + 2 * c;
                float b0 = bias[n0 + lcol], b1 = bias[n0 + lcol + 1];
                ts[(lcol    ) * T_PAD + lrow    ] = __float2half_rn(acc[mt][nt][0] + b0);
                ts[(lcol + 1) * T_PAD + lrow    ] = __float2half_rn(acc[mt][nt][1] + b1);
                ts[(lcol    ) * T_PAD + lrow + 8] = __float2half_rn(acc[mt][nt][2] + b0);
                ts[(lcol + 1) * T_PAD + lrow + 8] = __float2half_rn(acc[mt][nt][3] + b1);
            }
        }
        __syncthreads();
        const int bb = m0 >> 11;              // batch (SEQ = 2048)
        const int s0 = m0 & (SEQ - 1);
        // 128 cols x 128 tokens = 128 cols x 16 uint4-chunks (8 halves each)
#pragma unroll
        for (int i = 0; i < 8; i++) {
            int idx = tid + i * 256;          // 2048 chunks total
            int lcol = idx >> 4, ch = idx & 15;
            int col = n0 + lcol;              // global col = h*64 + d
            size_t drow = (size_t)((bb * NH + (col >> 6)) * 64 + (col & 63));
            *(uint4*)&ChT[drow * SEQ + s0 + ch * 8] =
                *(const uint4*)&ts[lcol * T_PAD + ch * 8];
        }
        return;
    }

#pragma unroll
    for (int mt = 0; mt < 4; mt++) {
#pragma unroll
        for (int nt = 0; nt < 4; nt++) {
            int row = m0 + wm * 64 + mt * 16 + r;
            int col = n0 + wn * 32 + nt * 8 + 2 * c;
            float b0 = bias[col], b1 = bias[col + 1];
            float f0 = acc[mt][nt][0] + b0, f1 = acc[mt][nt][1] + b1;
            float f2 = acc[mt][nt][2] + b0, f3 = acc[mt][nt][3] + b1;
            if (OUT == 0) {
                *(float2*)&Cf[(size_t)row * N + col]       = make_float2(f0, f1);
                *(float2*)&Cf[(size_t)(row + 8) * N + col] = make_float2(f2, f3);
            } else {
                *(uint32_t*)&Ch[(size_t)row * N + col]       = packh2(f0, f1);
                *(uint32_t*)&Ch[(size_t)(row + 8) * N + col] = packh2(f2, f3);
            }
        }
    }
}

// ---------------------------------------------------------------------------
// zdenom: rz = 1/sum_h e_h (fp16); stores e_h (fp16) to g_E[b][h][q][k]
// 3-stage cp.async, single sync per head, ldmatrix fragments.
// ---------------------------------------------------------------------------
namespace {
constexpr int Z_QT    = 18432;                 // Q tile 128 x 144B
constexpr int Z_KT    = 9216;                  // K tile 64 x 144B
constexpr int Z_STAGE = Z_QT + Z_KT;           // 27648
constexpr int Z_SMEM  = 3 * Z_STAGE;           // 82944
}

__global__ __launch_bounds__(256)
void zdenom_mma()
{
    extern __shared__ __align__(16) char smem[];
    const uint32_t sb = smem_u32(smem);
    const int tid = threadIdx.x, lane = tid & 31, wid = tid >> 5;
    const int r = lane >> 2, c = lane & 3;
    const int b = blockIdx.z, q0 = blockIdx.y * 128, k0 = blockIdx.x * 64;

    const int la = lane & 15;
    const int ka = (lane >> 4) * 16;
    const int lb = (lane & 7) + ((lane >> 4) & 1) * 8;
    const int kb = ((lane >> 3) & 1) * 16;

    auto issue = [&](int h, int s) {
        const uint32_t base = sb + s * Z_STAGE;
#pragma unroll
        for (int i = 0; i < 4; i++) {          // Q: 128 rows x 8 chunks
            int idx = tid + i * 256;
            int rr = idx >> 3, cc = idx & 7;
            cp16(base + rr * 144 + cc * 16,
                 g_q + (size_t)(b * SEQ + q0 + rr) * DM + h * 64 + cc * 8);
        }
#pragma unroll
        for (int i = 0; i < 2; i++) {          // K: 64 rows x 8 chunks
            int idx = tid + i * 256;
            int rr = idx >> 3, cc = idx & 7;
            cp16(base + Z_QT + rr * 144 + cc * 16,
                 g_k + (size_t)(b * SEQ + k0 + rr) * DM + h * 64 + cc * 8);
        }
        cp_commit();
    };

    issue(0, 0);
    issue(1, 1);

    float z[8][4];
#pragma unroll
    for (int i = 0; i < 8; i++)
#pragma unroll
        for (int j = 0; j < 4; j++) z[i][j] = 0.f;

    for (int h = 0; h < NH; h++) {
        if (h == NH - 1) cp_wait<0>(); else cp_wait<1>();
        __syncthreads();
        if (h + 2 < NH) issue(h + 2, (h + 2) % 3);
        const uint32_t st = sb + (h % 3) * Z_STAGE;

        float sc[8][4];
#pragma unroll
        for (int i = 0; i < 8; i++)
#pragma unroll
            for (int j = 0; j < 4; j++) sc[i][j] = 0.f;

#pragma unroll
        for (int kk = 0; kk < 4; kk++) {
            uint32_t aq[4], kp[4][4];
            ldsm4(aq, st + (uint32_t)(wid * 16 + la) * 144 + kk * 32 + ka);
            const uint32_t koff = st + Z_QT + (uint32_t)lb * 144 + kk * 32 + kb;
#pragma unroll
            for (int p = 0; p < 4; p++)
                ldsm4(kp[p], koff + p * (16 * 144));
#pragma unroll
            for (int nt = 0; nt < 8; nt++)
                mma16816(sc[nt], aq, &kp[nt >> 1][(nt & 1) * 2]);
        }

#pragma unroll
        for (int i = 0; i < 8; i++)
#pragma unroll
            for (int j = 0; j < 4; j++) {
                sc[i][j] = ex2(sc[i][j] * SCLOG2E);
                z[i][j] += sc[i][j];
            }
        {
            size_t eb = ((size_t)((b * NH + h) * SEQ) + q0 + wid * 16 + r) * SEQ + k0;
#pragma unroll
            for (int nt = 0; nt < 8; nt++) {
                *(uint32_t*)&g_E[eb + nt * 8 + 2 * c] = packh2(sc[nt][0], sc[nt][1]);
                *(uint32_t*)&g_E[eb + (size_t)8 * SEQ + nt * 8 + 2 * c] =
                    packh2(sc[nt][2], sc[nt][3]);
            }
        }
    }

#pragma unroll
    for (int nt = 0; nt < 8; nt++) {
        int q = q0 + wid * 16 + r;
        int col = k0 + nt * 8 + 2 * c;
        *(uint32_t*)&g_rz[(size_t)(b * SEQ + q) * SEQ + col] =
            packh2(frcp(z[nt][0]), frcp(z[nt][1]));
        *(uint32_t*)&g_rz[(size_t)(b * SEQ + q + 8) * SEQ + col] =
            packh2(frcp(z[nt][2]), frcp(z[nt][3]));
    }
}

// ---------------------------------------------------------------------------
// attn (PV only): p = E .* rz (half2 mul, rz preloaded fp16); acc += p @ V
// 3-stage cp.async, single sync per k-tile, ldmatrix fragments.
// ---------------------------------------------------------------------------
namespace {
constexpr int AE_T    = 18432;                 // E tile 128 x 144B
constexpr int AV_T    = 9216;                  // V tile 64 x 144B
constexpr int A_STAGE = AE_T + AV_T;           // 27648
constexpr int A_SMEM  = 3 * A_STAGE;           // 82944
}

__global__ __launch_bounds__(256)
void attn_mma()
{
    extern __shared__ __align__(16) char smem[];
    const uint32_t sb = smem_u32(smem);
    const int tid = threadIdx.x, lane = tid & 31, wid = tid >> 5;
    const int r = lane >> 2, c = lane & 3;
    const int b = blockIdx.z, h = blockIdx.y, q0 = blockIdx.x * 128;
    const int hc = h * 64;
    const __half* Eb = g_E + (size_t)(b * NH + h) * SEQ * SEQ;

    const int la = lane & 15;
    const int ka = (lane >> 4) * 16;
    const int lb = (lane & 7) + ((lane >> 4) & 1) * 8;
    const int kb = ((lane >> 3) & 1) * 16;

    auto issue = [&](int kt, int s) {
        const uint32_t base = sb + s * A_STAGE;
#pragma unroll
        for (int i = 0; i < 4; i++) {        // E: 128 rows x 8 chunks
            int idx = tid + i * 256;
            int rr = idx >> 3, cc = idx & 7;
            cp16(base + rr * 144 + cc * 16,
                 Eb + (size_t)(q0 + rr) * SEQ + kt * 64 + cc * 8);
        }
#pragma unroll
        for (int i = 0; i < 2; i++) {        // V: 64 rows x 8 chunks
            int idx = tid + i * 256;
            int r2 = idx >> 3, cc = idx & 7;
            cp16(base + AE_T + r2 * 144 + cc * 16,
                 g_vt + (size_t)((b * NH + h) * 64 + r2) * SEQ + kt * 64 + cc * 8);
        }
        cp_commit();
    };

    issue(0, 0);
    issue(1, 1);

    float acc[8][4];
#pragma unroll
    for (int i = 0; i < 8; i++)
#pragma unroll
        for (int j = 0; j < 4; j++) acc[i][j] = 0.f;

    const __half* Rz0 = g_rz + (size_t)(b * SEQ + q0 + wid * 16 + r) * SEQ + 2 * c;
    const __half* Rz1 = Rz0 + (size_t)8 * SEQ;

    const int KT = SEQ / 64;   // 32
    for (int kt = 0; kt < KT; kt++) {
        uint32_t rzh[4][4];
#pragma unroll
        for (int kk = 0; kk < 4; kk++) {
            rzh[kk][0] = *(const uint32_t*)&Rz0[kt * 64 + kk * 16];
            rzh[kk][1] = *(const uint32_t*)&Rz0[kt * 64 + kk * 16 + 8];
            rzh[kk][2] = *(const uint32_t*)&Rz1[kt * 64 + kk * 16];
            rzh[kk][3] = *(const uint32_t*)&Rz1[kt * 64 + kk * 16 + 8];
        }
        if (kt == KT - 1) cp_wait<0>(); else cp_wait<1>();
        __syncthreads();
        if (kt + 2 < KT) issue(kt + 2, (kt + 2) % 3);
        const uint32_t st = sb + (kt % 3) * A_STAGE;

#pragma unroll
        for (int kk = 0; kk < 4; kk++) {
            uint32_t ap[4];
            {
                uint32_t ef[4];
                ldsm4(ef, st + (uint32_t)(wid * 16 + la) * 144 + kk * 32 + ka);
                ap[0] = hmul2u(ef[0], rzh[kk][0]);   // (row,   k)
                ap[1] = hmul2u(ef[1], rzh[kk][2]);   // (row+8, k)
                ap[2] = hmul2u(ef[2], rzh[kk][1]);   // (row,   k+8)
                ap[3] = hmul2u(ef[3], rzh[kk][3]);   // (row+8, k+8)
            }
            uint32_t vp[4][4];
            const uint32_t voff = st + AE_T + (uint32_t)lb * 144 + kk * 32 + kb;
#pragma unroll
            for (int p = 0; p < 4; p++)
                ldsm4(vp[p], voff + p * (16 * 144));
#pragma unroll
            for (int dt = 0; dt < 8; dt++)
                mma16816(acc[dt], ap, &vp[dt >> 1][(dt & 1) * 2]);
        }
    }

    // epilogue: context -> fp16
#pragma unroll
    for (int dt = 0; dt < 8; dt++) {
        int row = b * SEQ + q0 + wid * 16 + r;
        int col = hc + dt * 8 + 2 * c;
        *(uint32_t*)&g_c[(size_t)row * DM + col]       = packh2(acc[dt][0], acc[dt][1]);
        *(uint32_t*)&g_c[(size_t)(row + 8) * DM + col] = packh2(acc[dt][2], acc[dt][3]);
    }
}

// ---------------------------------------------------------------------------
extern "C" void kernel_launch(void* const* d_in, const int* in_sizes, int n_in,
                              void* d_out, int out_size)
{
    (void)in_sizes; (void)n_in; (void)out_size;
    const float* x  = (const float*)d_in[0];
    const float* Wq = (const float*)d_in[1];
    const float* bq = (const float*)d_in[2];
    const float* Wk = (const float*)d_in[3];
    const float* bk = (const float*)d_in[4];
    const float* Wv = (const float*)d_in[5];
    const float* bv = (const float*)d_in[6];
    const float* Wo = (const float*)d_in[7];
    const float* bo = (const float*)d_in[8];
    float* out = (float*)d_out;

    __half *xp, *wp, *qp, *kp, *vtp, *cp;
    cudaGetSymbolAddress((void**)&xp, g_x);
    cudaGetSymbolAddress((void**)&wp, g_w);
    cudaGetSymbolAddress((void**)&qp, g_q);
    cudaGetSymbolAddress((void**)&kp, g_k);
    cudaGetSymbolAddress((void**)&vtp, g_vt);
    cudaGetSymbolAddress((void**)&cp, g_c);

    cudaFuncSetAttribute(gemm_mma<0>, cudaFuncAttributeMaxDynamicSharedMemorySize, G_SMEM);
    cudaFuncSetAttribute(gemm_mma<1>, cudaFuncAttributeMaxDynamicSharedMemorySize, G_SMEM);
    cudaFuncSetAttribute(zdenom_mma,  cudaFuncAttributeMaxDynamicSharedMemorySize, Z_SMEM);
    cudaFuncSetAttribute(attn_mma,    cudaFuncAttributeMaxDynamicSharedMemorySize, A_SMEM);

    const int NX = NTOK * DM;   // 4M
    const int NW = DM * DM;     // 1M
    cvt_all<<<dim3(NX / 1024, 2), 256>>>(x, Wq, Wk, Wv, Wo, xp, wp);

    // fused Q/K/V projections; z==2 (V) writes transposed per-head layout
    gemm_mma<1><<<dim3(DM / 128, NTOK / 128, 3), 256, G_SMEM>>>(
        xp, wp + 0 * NW, wp + 1 * NW, wp + 2 * NW,
        bq, bk, bv, nullptr, qp, kp, vtp, NTOK, DM, DM);

    zdenom_mma<<<dim3(SEQ / 64, SEQ / 128, BT), 256, Z_SMEM>>>();

    attn_mma<<<dim3(SEQ / 128, NH, BT), 256, A_SMEM>>>();

    gemm_mma<0><<<dim3(DM / 128, NTOK / 128, 1), 256, G_SMEM>>>(
        cp, wp + 3 * NW, wp + 3 * NW, wp + 3 * NW,
        bo, bo, bo, out, nullptr, nullptr, nullptr, NTOK, DM, DM);
}